// round 7
// baseline (speedup 1.0000x reference)
#include <cuda_runtime.h>
#include <math.h>

#define BATCH   2
#define LSEQ    2048
#define DMODEL  1024
#define DINNER  2048
#define DSTATE  16
#define DTRANK  64
#define XDBLW   (DTRANK + 2*DSTATE)   // 96
#define ROWS    (BATCH*LSEQ)          // 4096
#define EPSLN   1e-5f

// ---------------- scratch (static device globals; no allocation) ----------------
__device__ float g_xn   [(size_t)ROWS * DMODEL];        // 16 MB
__device__ float g_xz   [(size_t)ROWS * 2 * DINNER];    // 64 MB
__device__ float g_u    [(size_t)ROWS * DINNER];        // 32 MB
__device__ float g_xdbl [(size_t)ROWS * XDBLW];         // 1.5 MB
__device__ float g_delta[(size_t)ROWS * DINNER];        // 32 MB
__device__ float g_ybar [(size_t)ROWS * DINNER];        // 32 MB

// Device-side scratch-buffer selector: host code never touches device symbols.
#define BUF_XN    0
#define BUF_XZ    1
#define BUF_U     2
#define BUF_XDBL  3
#define BUF_DELTA 4
#define BUF_YBAR  5
#define BUF_EXT   (-1)

__device__ __forceinline__ float* sel_buf(int s) {
    switch (s) {
        case BUF_XN:    return g_xn;
        case BUF_XZ:    return g_xz;
        case BUF_U:     return g_u;
        case BUF_XDBL:  return g_xdbl;
        case BUF_DELTA: return g_delta;
        case BUF_YBAR:  return g_ybar;
        default:        return nullptr;
    }
}

// ---------------- LayerNorm: one block per row of 1024 ----------------
__global__ void ln_kernel(const float* __restrict__ x,
                          const float* __restrict__ w,
                          const float* __restrict__ b)
{
    int row = blockIdx.x;
    int tid = threadIdx.x;                 // 256 threads, 4 floats each
    const float4* xr = (const float4*)(x + (size_t)row * DMODEL);
    float4 v = xr[tid];
    float s  = v.x + v.y + v.z + v.w;
    float sq = v.x*v.x + v.y*v.y + v.z*v.z + v.w*v.w;
    #pragma unroll
    for (int o = 16; o > 0; o >>= 1) {
        s  += __shfl_down_sync(0xffffffffu, s,  o);
        sq += __shfl_down_sync(0xffffffffu, sq, o);
    }
    __shared__ float ss[8], sqs[8];
    int wid = tid >> 5, lid = tid & 31;
    if (lid == 0) { ss[wid] = s; sqs[wid] = sq; }
    __syncthreads();
    __shared__ float s_mu, s_rstd;
    if (tid == 0) {
        float ts = 0.f, tq = 0.f;
        #pragma unroll
        for (int i = 0; i < 8; i++) { ts += ss[i]; tq += sqs[i]; }
        float mu  = ts * (1.f / DMODEL);
        float var = tq * (1.f / DMODEL) - mu * mu;
        s_mu = mu;
        s_rstd = rsqrtf(var + EPSLN);
    }
    __syncthreads();
    float mu = s_mu, rstd = s_rstd;
    float4 w4 = ((const float4*)w)[tid];
    float4 b4 = ((const float4*)b)[tid];
    float4 o4;
    o4.x = (v.x - mu) * rstd * w4.x + b4.x;
    o4.y = (v.y - mu) * rstd * w4.y + b4.y;
    o4.z = (v.z - mu) * rstd * w4.z + b4.z;
    o4.w = (v.w - mu) * rstd * w4.w + b4.w;
    ((float4*)(g_xn + (size_t)row * DMODEL))[tid] = o4;
}

// ---------------- generic NT SGEMM: C[M,N] = A[M,K] * B[N,K]^T (+ epilogue) ----
// A is a scratch buffer (a_sel); B is an external weight; C is scratch or ext.
// epi: 0 = none; 1 = add residual epi_ptr[row*ldc+col]; 2 = softplus(acc + epi_ptr[col])
#define BM 128
#define BN 128
#define BK 16

__device__ __forceinline__ float softplusf(float x) {
    return (x > 20.f) ? x : log1pf(__expf(x));
}

__global__ __launch_bounds__(256)
void sgemm_nt(int a_sel, const float* __restrict__ B, int c_sel, float* Cext,
              int M, int N, int K, int lda, int ldb, int ldc,
              int epi, const float* __restrict__ epi_ptr)
{
    const float* A = sel_buf(a_sel);
    float* C = (c_sel == BUF_EXT) ? Cext : sel_buf(c_sel);

    __shared__ float As[BK][BM];
    __shared__ float Bs[BK][BN];
    int bm = blockIdx.y * BM;
    int bn = blockIdx.x * BN;
    int tid = threadIdx.x;           // 256
    int tx = tid & 15, ty = tid >> 4;

    float acc[8][8];
    #pragma unroll
    for (int i = 0; i < 8; i++)
        #pragma unroll
        for (int j = 0; j < 8; j++) acc[i][j] = 0.f;

    for (int k0 = 0; k0 < K; k0 += BK) {
        #pragma unroll
        for (int i = 0; i < 2; i++) {
            int idx = tid + i * 256;
            int row = idx >> 2, kc = (idx & 3) * 4;
            float4 v = *(const float4*)(A + (size_t)(bm + row) * lda + k0 + kc);
            As[kc + 0][row] = v.x; As[kc + 1][row] = v.y;
            As[kc + 2][row] = v.z; As[kc + 3][row] = v.w;
        }
        #pragma unroll
        for (int i = 0; i < 2; i++) {
            int idx = tid + i * 256;
            int row = idx >> 2, kc = (idx & 3) * 4;
            float4 v = make_float4(0.f, 0.f, 0.f, 0.f);
            if (bn + row < N)
                v = *(const float4*)(B + (size_t)(bn + row) * ldb + k0 + kc);
            Bs[kc + 0][row] = v.x; Bs[kc + 1][row] = v.y;
            Bs[kc + 2][row] = v.z; Bs[kc + 3][row] = v.w;
        }
        __syncthreads();
        #pragma unroll
        for (int k = 0; k < BK; k++) {
            float ra[8], rb[8];
            *(float4*)(ra + 0) = *(const float4*)&As[k][ty * 8 + 0];
            *(float4*)(ra + 4) = *(const float4*)&As[k][ty * 8 + 4];
            *(float4*)(rb + 0) = *(const float4*)&Bs[k][tx * 8 + 0];
            *(float4*)(rb + 4) = *(const float4*)&Bs[k][tx * 8 + 4];
            #pragma unroll
            for (int i = 0; i < 8; i++)
                #pragma unroll
                for (int j = 0; j < 8; j++)
                    acc[i][j] = fmaf(ra[i], rb[j], acc[i][j]);
        }
        __syncthreads();
    }

    #pragma unroll
    for (int i = 0; i < 8; i++) {
        int row = bm + ty * 8 + i;
        #pragma unroll
        for (int j = 0; j < 8; j++) {
            int col = bn + tx * 8 + j;
            if (col < N) {
                float v = acc[i][j];
                if (epi == 1) v += epi_ptr[(size_t)row * ldc + col];
                else if (epi == 2) v = softplusf(v + epi_ptr[col]);
                C[(size_t)row * ldc + col] = v;
            }
        }
    }
}

// ---------------- causal depthwise conv (width 4) + bias + SiLU ----------------
__global__ void conv_silu_kernel(const float* __restrict__ cw,
                                 const float* __restrict__ cb)
{
    int idx = blockIdx.x * blockDim.x + threadIdx.x;   // ROWS*DINNER
    if (idx >= ROWS * DINNER) return;
    int d   = idx & (DINNER - 1);
    int row = idx >> 11;                                // b*LSEQ + l
    int l   = row & (LSEQ - 1);
    float acc = cb[d];
    #pragma unroll
    for (int j = 0; j < 4; j++) {
        int li = l - 3 + j;
        float v = (li >= 0) ? g_xz[(size_t)(row - 3 + j) * (2 * DINNER) + d] : 0.f;
        acc = fmaf(cw[d * 4 + j], v, acc);
    }
    float sig = 1.f / (1.f + __expf(-acc));
    g_u[idx] = acc * sig;
}

// ---------------- selective scan (+skip D*u, gate silu(z)) ----------------
// one thread per (b, d); h[16] in registers; fast path: dA_s = E^(s+1)
__global__ void scan_kernel(const float* __restrict__ A_log,
                            const float* __restrict__ Dp)
{
    int gid = blockIdx.x * blockDim.x + threadIdx.x;   // 0..4095
    if (gid >= BATCH * DINNER) return;
    int b = gid >> 11;
    int d = gid & (DINNER - 1);

    float Av[DSTATE];
    #pragma unroll
    for (int s = 0; s < DSTATE; s++) Av[s] = -__expf(A_log[d * DSTATE + s]);
    float A0 = Av[0];
    bool fast = true;
    #pragma unroll
    for (int s = 0; s < DSTATE; s++) {
        float ideal = A0 * (float)(s + 1);
        if (fabsf(Av[s] - ideal) > 1e-4f * fabsf(ideal) + 1e-6f) fast = false;
    }
    float Dd = Dp[d];

    float h[DSTATE];
    #pragma unroll
    for (int s = 0; s < DSTATE; s++) h[s] = 0.f;

    size_t base = (size_t)b * LSEQ;

    // prefetch l = 0
    float dlt = g_delta[base * DINNER + d];
    float uu  = g_u[base * DINNER + d];
    float zz  = g_xz[base * (2 * DINNER) + DINNER + d];
    const float* xr = g_xdbl + base * XDBLW;
    float4 B0 = *(const float4*)(xr + 64), B1 = *(const float4*)(xr + 68);
    float4 B2 = *(const float4*)(xr + 72), B3 = *(const float4*)(xr + 76);
    float4 C0 = *(const float4*)(xr + 80), C1 = *(const float4*)(xr + 84);
    float4 C2 = *(const float4*)(xr + 88), C3 = *(const float4*)(xr + 92);

    for (int l = 0; l < LSEQ; l++) {
        float cdlt = dlt, cuu = uu, czz = zz;
        float Bv[16], Cv[16];
        *(float4*)(Bv + 0) = B0;  *(float4*)(Bv + 4)  = B1;
        *(float4*)(Bv + 8) = B2;  *(float4*)(Bv + 12) = B3;
        *(float4*)(Cv + 0) = C0;  *(float4*)(Cv + 4)  = C1;
        *(float4*)(Cv + 8) = C2;  *(float4*)(Cv + 12) = C3;

        if (l + 1 < LSEQ) {   // prefetch next step
            size_t r = base + l + 1;
            dlt = g_delta[r * DINNER + d];
            uu  = g_u[r * DINNER + d];
            zz  = g_xz[r * (2 * DINNER) + DINNER + d];
            const float* xn = g_xdbl + r * XDBLW;
            B0 = *(const float4*)(xn + 64); B1 = *(const float4*)(xn + 68);
            B2 = *(const float4*)(xn + 72); B3 = *(const float4*)(xn + 76);
            C0 = *(const float4*)(xn + 80); C1 = *(const float4*)(xn + 84);
            C2 = *(const float4*)(xn + 88); C3 = *(const float4*)(xn + 92);
        }

        float du = cdlt * cuu;
        float y0 = 0.f, y1 = 0.f;
        if (fast) {
            float E = __expf(cdlt * A0);
            float p = E;
            #pragma unroll
            for (int s = 0; s < DSTATE; s++) {
                h[s] = fmaf(p, h[s], du * Bv[s]);
                if (s & 1) y1 = fmaf(h[s], Cv[s], y1);
                else       y0 = fmaf(h[s], Cv[s], y0);
                p *= E;
            }
        } else {
            #pragma unroll
            for (int s = 0; s < DSTATE; s++) {
                float dA = __expf(cdlt * Av[s]);
                h[s] = fmaf(dA, h[s], du * Bv[s]);
                if (s & 1) y1 = fmaf(h[s], Cv[s], y1);
                else       y0 = fmaf(h[s], Cv[s], y0);
            }
        }
        float y = y0 + y1 + Dd * cuu;
        float sig = 1.f / (1.f + __expf(-czz));
        g_ybar[(base + l) * DINNER + d] = y * (czz * sig);
    }
}

// ---------------- launch (pure launch sequence; no CUDA API calls) ----------------
extern "C" void kernel_launch(void* const* d_in, const int* in_sizes, int n_in,
                              void* d_out, int out_size)
{
    const float* x      = (const float*)d_in[0];
    const float* norm_w = (const float*)d_in[1];
    const float* norm_b = (const float*)d_in[2];
    const float* W_in   = (const float*)d_in[3];
    const float* conv_w = (const float*)d_in[4];
    const float* conv_b = (const float*)d_in[5];
    const float* W_x    = (const float*)d_in[6];
    const float* W_dt   = (const float*)d_in[7];
    const float* b_dt   = (const float*)d_in[8];
    const float* A_log  = (const float*)d_in[9];
    const float* Dp     = (const float*)d_in[10];
    const float* W_out  = (const float*)d_in[11];
    float* out = (float*)d_out;

    // 1) LayerNorm -> g_xn
    ln_kernel<<<ROWS, 256>>>(x, norm_w, norm_b);

    // 2) in_proj: g_xz[4096,4096] = g_xn[4096,1024] @ W_in[4096,1024]^T
    {
        dim3 grid((2 * DINNER + BN - 1) / BN, ROWS / BM);
        sgemm_nt<<<grid, 256>>>(BUF_XN, W_in, BUF_XZ, nullptr,
                                ROWS, 2 * DINNER, DMODEL,
                                DMODEL, DMODEL, 2 * DINNER, 0, nullptr);
    }

    // 3) depthwise conv + SiLU -> g_u
    {
        int total = ROWS * DINNER;
        conv_silu_kernel<<<(total + 255) / 256, 256>>>(conv_w, conv_b);
    }

    // 4) x_proj: g_xdbl[4096,96] = g_u @ W_x[96,2048]^T
    {
        dim3 grid((XDBLW + BN - 1) / BN, ROWS / BM);
        sgemm_nt<<<grid, 256>>>(BUF_U, W_x, BUF_XDBL, nullptr,
                                ROWS, XDBLW, DINNER,
                                DINNER, DINNER, XDBLW, 0, nullptr);
    }

    // 5) dt_proj + softplus: g_delta = softplus(g_xdbl[:, :64] @ W_dt^T + b_dt)
    {
        dim3 grid((DINNER + BN - 1) / BN, ROWS / BM);
        sgemm_nt<<<grid, 256>>>(BUF_XDBL, W_dt, BUF_DELTA, nullptr,
                                ROWS, DINNER, DTRANK,
                                XDBLW, DTRANK, DINNER, 2, b_dt);
    }

    // 6) selective scan + skip + gate -> g_ybar
    scan_kernel<<<(BATCH * DINNER + 63) / 64, 64>>>(A_log, Dp);

    // 7) out_proj + residual: out = g_ybar @ W_out^T + x
    {
        dim3 grid((DMODEL + BN - 1) / BN, ROWS / BM);
        sgemm_nt<<<grid, 256>>>(BUF_YBAR, W_out, BUF_EXT, out,
                                ROWS, DMODEL, DINNER,
                                DINNER, DINNER, DMODEL, 1, x);
    }
}

// round 10
// speedup vs baseline: 1.4908x; 1.4908x over previous
#include <cuda_runtime.h>
#include <cuda_bf16.h>
#include <stdint.h>
#include <math.h>

#define BATCH   2
#define LSEQ    2048
#define DMODEL  1024
#define DINNER  2048
#define DSTATE  16
#define DTRANK  64
#define XDBLW   (DTRANK + 2*DSTATE)   // 96
#define ROWS    (BATCH*LSEQ)          // 4096
#define EPSLN   1e-5f

// ================= scratch (static device globals; no allocation) =================
__device__ float g_xz   [(size_t)ROWS * 2 * DINNER];    // 64 MB
__device__ float g_u    [(size_t)ROWS * DINNER];        // 32 MB
__device__ float g_xdbl [(size_t)ROWS * XDBLW];         // 1.5 MB
__device__ float g_delta[(size_t)ROWS * DINNER];        // 32 MB
// split-bf16 planes (hi, lo)
__device__ __nv_bfloat16 g_xnh[(size_t)ROWS*DMODEL],  g_xnl[(size_t)ROWS*DMODEL];
__device__ __nv_bfloat16 g_uh [(size_t)ROWS*DINNER],  g_ul [(size_t)ROWS*DINNER];
__device__ __nv_bfloat16 g_xdh[(size_t)ROWS*XDBLW],   g_xdl[(size_t)ROWS*XDBLW];
__device__ __nv_bfloat16 g_ybh[(size_t)ROWS*DINNER],  g_ybl[(size_t)ROWS*DINNER];
__device__ __nv_bfloat16 g_winh[(size_t)2*DINNER*DMODEL], g_winl[(size_t)2*DINNER*DMODEL];
__device__ __nv_bfloat16 g_wxh [(size_t)XDBLW*DINNER],    g_wxl [(size_t)XDBLW*DINNER];
__device__ __nv_bfloat16 g_wdth[(size_t)DINNER*DTRANK],   g_wdtl[(size_t)DINNER*DTRANK];
__device__ __nv_bfloat16 g_wouth[(size_t)DMODEL*DINNER],  g_woutl[(size_t)DMODEL*DINNER];

#define PL_XN 0
#define PL_U 1
#define PL_XD 2
#define PL_YB 3
#define PL_WIN 4
#define PL_WX 5
#define PL_WDT 6
#define PL_WOUT 7
__device__ __forceinline__ void sel_planes(int s, const __nv_bfloat16*& h, const __nv_bfloat16*& l) {
    switch (s) {
        case PL_XN:  h = g_xnh;  l = g_xnl;  break;
        case PL_U:   h = g_uh;   l = g_ul;   break;
        case PL_XD:  h = g_xdh;  l = g_xdl;  break;
        case PL_YB:  h = g_ybh;  l = g_ybl;  break;
        case PL_WIN: h = g_winh; l = g_winl; break;
        case PL_WX:  h = g_wxh;  l = g_wxl;  break;
        case PL_WDT: h = g_wdth; l = g_wdtl; break;
        default:     h = g_wouth;l = g_woutl;break;
    }
}
#define CF_XZ 0
#define CF_XDBL 1
#define CF_DELTA 2
#define CF_EXT (-1)

// Arch-specific (sm_103a) feature gate: tcgen05 only exists on the 'a' target.
#if defined(__CUDA_ARCH__) && (defined(__CUDA_ARCH_FEAT_SM103_ALL) || defined(__CUDA_ARCH_FEAT_SM100_ALL))
#define HAS_TCGEN05 1
#else
#define HAS_TCGEN05 0
#endif

// ================= helpers =================
__device__ __forceinline__ float softplusf(float x) {
    return (x > 20.f) ? x : log1pf(__expf(x));
}
__device__ __forceinline__ void split1(float v, __nv_bfloat16& h, __nv_bfloat16& l) {
    h = __float2bfloat16(v);
    l = __float2bfloat16(v - __bfloat162float(h));
}

#if HAS_TCGEN05
__device__ __forceinline__ uint32_t smem_u32(const void* p) {
    uint32_t a;
    asm("{ .reg .u64 t; cvta.to.shared.u64 t, %1; cvt.u32.u64 %0, t; }" : "=r"(a) : "l"(p));
    return a;
}
__device__ __forceinline__ uint32_t elect1() {
    uint32_t p;
    asm volatile("{\n\t.reg .pred p;\n\telect.sync _|p, 0xFFFFFFFF;\n\tselp.b32 %0, 1, 0, p;\n\t}" : "=r"(p));
    return p;
}
__device__ __forceinline__ uint64_t mkdesc(uint32_t addr) {
    const uint64_t base = (uint64_t(2) << 61) | (uint64_t(1) << 46)
                        | (uint64_t(64) << 32) | (uint64_t(1) << 16);   // SW128, v1, SBO=64, LBO=1
    return base | ((uint64_t)(addr >> 4) & 0x3FFF);
}
__device__ __forceinline__ void mma_bf16_ss(uint32_t d, uint64_t da, uint64_t db, uint32_t idesc, uint32_t en) {
    asm volatile("{\n\t.reg .pred p;\n\tsetp.ne.u32 p, %5, 0;\n\t"
        "tcgen05.mma.cta_group::1.kind::f16 [%0], %1, %2, %3, {%4, %4, %4, %4}, p;\n\t}"
        :: "r"(d), "l"(da), "l"(db), "r"(idesc), "r"(0u), "r"(en) : "memory");
}
#define TC_ALLOC(sm, n)   asm volatile("tcgen05.alloc.cta_group::1.sync.aligned.shared::cta.b32 [%0], %1;" :: "r"(sm), "r"(n) : "memory")
#define TC_RELQ()         asm volatile("tcgen05.relinquish_alloc_permit.cta_group::1.sync.aligned;")
#define TC_DEALLOC(t, n)  asm volatile("tcgen05.dealloc.cta_group::1.sync.aligned.b32 %0, %1;" :: "r"(t), "r"(n))
#define TC_COMMIT(mb)     asm volatile("tcgen05.commit.cta_group::1.mbarrier::arrive::one.shared::cluster.b64 [%0];" :: "r"(mb) : "memory")
#define TC_WAIT_LD()      asm volatile("tcgen05.wait::ld.sync.aligned;" ::: "memory")
#define TC_FENCE_AFTER()  asm volatile("tcgen05.fence::after_thread_sync;" ::: "memory")
#define TC_FENCE_BEFORE() asm volatile("tcgen05.fence::before_thread_sync;" ::: "memory")
#define FENCE_ASYNC()     asm volatile("fence.proxy.async.shared::cta;" ::: "memory")
#define MBAR_INIT(mb, c)  asm volatile("mbarrier.init.shared.b64 [%0], %1;" :: "r"(mb), "r"(c) : "memory")
#define MBAR_INVAL(mb)    asm volatile("mbarrier.inval.shared.b64 [%0];" :: "r"(mb) : "memory")
#define MBAR_WAIT(mb, ph) do { \
    uint32_t _m = (mb), _p = (ph), _done; \
    asm volatile("{\n\t.reg .pred p;\n\tmbarrier.try_wait.parity.acquire.cta.shared::cta.b64 p, [%1], %2;\n\tselp.b32 %0, 1, 0, p;\n\t}" \
        : "=r"(_done) : "r"(_m), "r"(_p) : "memory"); \
    if (!_done) { \
        asm volatile("{\n\t.reg .pred P1;\n\tWL%=:\n\tmbarrier.try_wait.parity.acquire.cta.shared::cta.b64 P1, [%0], %1, 0x989680;\n\t@P1 bra.uni WD%=;\n\tbra.uni WL%=;\n\tWD%=:\n\t}" \
            :: "r"(_m), "r"(_p) : "memory"); \
    } \
} while (0)
#define LDTM32(r, addr) \
    asm volatile("tcgen05.ld.sync.aligned.32x32b.x32.b32 " \
        "{%0, %1, %2, %3, %4, %5, %6, %7, %8, %9, %10, %11, %12, %13, %14, %15, " \
        " %16, %17, %18, %19, %20, %21, %22, %23, %24, %25, %26, %27, %28, %29, %30, %31}, [%32];" \
        : "=r"((r)[0]),  "=r"((r)[1]),  "=r"((r)[2]),  "=r"((r)[3]), \
          "=r"((r)[4]),  "=r"((r)[5]),  "=r"((r)[6]),  "=r"((r)[7]), \
          "=r"((r)[8]),  "=r"((r)[9]),  "=r"((r)[10]), "=r"((r)[11]), \
          "=r"((r)[12]), "=r"((r)[13]), "=r"((r)[14]), "=r"((r)[15]), \
          "=r"((r)[16]), "=r"((r)[17]), "=r"((r)[18]), "=r"((r)[19]), \
          "=r"((r)[20]), "=r"((r)[21]), "=r"((r)[22]), "=r"((r)[23]), \
          "=r"((r)[24]), "=r"((r)[25]), "=r"((r)[26]), "=r"((r)[27]), \
          "=r"((r)[28]), "=r"((r)[29]), "=r"((r)[30]), "=r"((r)[31]) \
        : "r"(addr))
#define SW128(x) ((x) ^ (((x) >> 3) & 0x70))
#endif  // HAS_TCGEN05

// ================= LayerNorm -> split planes =================
__global__ void ln_kernel(const float* __restrict__ x,
                          const float* __restrict__ w,
                          const float* __restrict__ b)
{
    int row = blockIdx.x;
    int tid = threadIdx.x;                 // 256 threads, 4 floats each
    const float4* xr = (const float4*)(x + (size_t)row * DMODEL);
    float4 v = xr[tid];
    float s  = v.x + v.y + v.z + v.w;
    float sq = v.x*v.x + v.y*v.y + v.z*v.z + v.w*v.w;
    #pragma unroll
    for (int o = 16; o > 0; o >>= 1) {
        s  += __shfl_down_sync(0xffffffffu, s,  o);
        sq += __shfl_down_sync(0xffffffffu, sq, o);
    }
    __shared__ float ss[8], sqs[8];
    int wid = tid >> 5, lid = tid & 31;
    if (lid == 0) { ss[wid] = s; sqs[wid] = sq; }
    __syncthreads();
    __shared__ float s_mu, s_rstd;
    if (tid == 0) {
        float ts = 0.f, tq = 0.f;
        #pragma unroll
        for (int i = 0; i < 8; i++) { ts += ss[i]; tq += sqs[i]; }
        float mu  = ts * (1.f / DMODEL);
        float var = tq * (1.f / DMODEL) - mu * mu;
        s_mu = mu; s_rstd = rsqrtf(var + EPSLN);
    }
    __syncthreads();
    float mu = s_mu, rstd = s_rstd;
    float4 w4 = ((const float4*)w)[tid];
    float4 b4 = ((const float4*)b)[tid];
    float o0 = (v.x - mu) * rstd * w4.x + b4.x;
    float o1 = (v.y - mu) * rstd * w4.y + b4.y;
    float o2 = (v.z - mu) * rstd * w4.z + b4.z;
    float o3 = (v.w - mu) * rstd * w4.w + b4.w;
    __nv_bfloat16 h0,h1,h2,h3,l0,l1,l2,l3;
    split1(o0,h0,l0); split1(o1,h1,l1); split1(o2,h2,l2); split1(o3,h3,l3);
    size_t o = (size_t)row * DMODEL + tid * 4;
    *(__nv_bfloat162*)(g_xnh + o)     = __halves2bfloat162(h0, h1);
    *(__nv_bfloat162*)(g_xnh + o + 2) = __halves2bfloat162(h2, h3);
    *(__nv_bfloat162*)(g_xnl + o)     = __halves2bfloat162(l0, l1);
    *(__nv_bfloat162*)(g_xnl + o + 2) = __halves2bfloat162(l2, l3);
}

// ================= fp32 -> split bf16 weight conversion =================
__global__ void cvt_split(const float* __restrict__ src, int dsel, int n4)
{
    __nv_bfloat16 *dh, *dl;
    switch (dsel) {
        case 0:  dh = g_winh;  dl = g_winl;  break;
        case 1:  dh = g_wxh;   dl = g_wxl;   break;
        case 2:  dh = g_wdth;  dl = g_wdtl;  break;
        default: dh = g_wouth; dl = g_woutl; break;
    }
    int i = blockIdx.x * blockDim.x + threadIdx.x;
    if (i >= n4) return;
    float4 v = ((const float4*)src)[i];
    __nv_bfloat16 h0,h1,h2,h3,l0,l1,l2,l3;
    split1(v.x,h0,l0); split1(v.y,h1,l1); split1(v.z,h2,l2); split1(v.w,h3,l3);
    size_t o = (size_t)i * 4;
    *(__nv_bfloat162*)(dh + o)     = __halves2bfloat162(h0, h1);
    *(__nv_bfloat162*)(dh + o + 2) = __halves2bfloat162(h2, h3);
    *(__nv_bfloat162*)(dl + o)     = __halves2bfloat162(l0, l1);
    *(__nv_bfloat162*)(dl + o + 2) = __halves2bfloat162(l2, l3);
}

// ================= split-bf16 NT GEMM (tcgen05 on sm_103a; FFMA fallback) ========
// C[4096, Ntot] = A[4096,K] * B[Ntot,K]^T; A,B given as (hi,lo) bf16 plane pairs.
// Tile: 128 x 128. epi: 0 none; 1 +epi[row*ldc+col]; 2 softplus(+epi[col]); 3 also split->xdbl planes
#define KC       64
#define PLANE_B  16384           // 128 rows * 128 bytes
#define STAGE_B  (4*PLANE_B)     // Ahi, Alo, Bhi, Blo
#define SMD      1024
#define GEMM_SMEM (SMD + 2*STAGE_B)   // 132096

#if HAS_TCGEN05
__device__ __forceinline__ void load_stage(char* smem, int s, int c,
    const __nv_bfloat16* __restrict__ Ah, const __nv_bfloat16* __restrict__ Al,
    const __nv_bfloat16* __restrict__ Bh, const __nv_bfloat16* __restrict__ Bl,
    int lda, int ldb, int bm, int bn, int Ntot, int tid)
{
    char* base = smem + SMD + s * STAGE_B;
    int kb = c * KC;
    #pragma unroll
    for (int i = 0; i < 4; i++) {
        int idx = tid + i * 256;
        int rowi = idx >> 3, u16 = idx & 7;
        uint32_t off = SW128((uint32_t)(rowi * 128 + u16 * 16));
        size_t aoff = (size_t)(bm + rowi) * lda + kb + u16 * 8;
        *(uint4*)(base + off)           = *(const uint4*)(Ah + aoff);
        *(uint4*)(base + PLANE_B + off) = *(const uint4*)(Al + aoff);
        uint4 vh = make_uint4(0,0,0,0), vl = make_uint4(0,0,0,0);
        if (bn + rowi < Ntot) {
            size_t boff = (size_t)(bn + rowi) * ldb + kb + u16 * 8;
            vh = *(const uint4*)(Bh + boff);
            vl = *(const uint4*)(Bl + boff);
        }
        *(uint4*)(base + 2*PLANE_B + off) = vh;
        *(uint4*)(base + 3*PLANE_B + off) = vl;
    }
}
#endif

__global__ __launch_bounds__(256)
void tc_gemm(int a_sel, int b_sel, int c_sel, float* __restrict__ Cext,
             int Ntot, int K, int lda, int ldb, int ldc,
             int epi, const float* __restrict__ epi_ptr)
{
    extern __shared__ char smem[];
    const __nv_bfloat16 *Ah, *Al, *Bh, *Bl;
    sel_planes(a_sel, Ah, Al);
    sel_planes(b_sel, Bh, Bl);
    float* C;
    switch (c_sel) {
        case CF_XZ:    C = g_xz;    break;
        case CF_XDBL:  C = g_xdbl;  break;
        case CF_DELTA: C = g_delta; break;
        default:       C = Cext;    break;
    }
    int tid = threadIdx.x;
    int bm = blockIdx.y * 128;
    int bn = blockIdx.x * 128;

#if HAS_TCGEN05
    uint32_t sb = smem_u32(smem);
    int wid = tid >> 5, lid = tid & 31;

    if (wid == 0) { TC_ALLOC(sb + 0, 128); TC_RELQ(); }
    if (tid == 0) { MBAR_INIT(sb + 8, 1); MBAR_INIT(sb + 16, 1); MBAR_INIT(sb + 24, 1); }
    __syncthreads();
    uint32_t tmem;
    asm volatile("ld.shared.b32 %0, [%1];" : "=r"(tmem) : "r"(sb + 0));

    const uint32_t idesc = (1u << 4) | (1u << 7) | (1u << 10)
                         | (16u << 17) | (8u << 24);   // F32 acc, bf16 a/b, N=128, M=128
    int NC = K / KC;

    load_stage(smem, 0, 0, Ah, Al, Bh, Bl, lda, ldb, bm, bn, Ntot, tid);
    FENCE_ASYNC();
    __syncthreads();

    int wcnt0 = 0, wcnt1 = 0;
    for (int c = 0; c < NC; c++) {
        int s = c & 1;
        if (wid == 0 && elect1()) {
            uint32_t stg = sb + SMD + s * STAGE_B;
            uint64_t dAh = mkdesc(stg), dAl = mkdesc(stg + PLANE_B);
            uint64_t dBh = mkdesc(stg + 2 * PLANE_B), dBl = mkdesc(stg + 3 * PLANE_B);
            #pragma unroll
            for (int k = 0; k < 4; k++) {       // K=16 per MMA, desc += 2 per step
                mma_bf16_ss(tmem, dAh + k*2, dBh + k*2, idesc, (c == 0 && k == 0) ? 0u : 1u);
                mma_bf16_ss(tmem, dAl + k*2, dBh + k*2, idesc, 1u);
                mma_bf16_ss(tmem, dAh + k*2, dBl + k*2, idesc, 1u);
            }
            TC_COMMIT(sb + 8 + 8 * s);
        }
        if (c + 1 < NC) {
            int t = s ^ 1;
            if (c >= 1) {
                int ph = ((t == 0) ? wcnt0 : wcnt1) & 1;
                MBAR_WAIT(sb + 8 + 8 * t, ph);
                if (t == 0) wcnt0++; else wcnt1++;
            }
            load_stage(smem, t, c + 1, Ah, Al, Bh, Bl, lda, ldb, bm, bn, Ntot, tid);
            FENCE_ASYNC();
            __syncthreads();
        }
    }
    if (wid == 0 && elect1()) TC_COMMIT(sb + 24);
    MBAR_WAIT(sb + 24, 0);
    TC_FENCE_AFTER();

    // epilogue: warps 0-3 cols [0,64), warps 4-7 cols [64,128); rows by subpartition
    {
        int sub = wid & 3;
        int row = bm + sub * 32 + lid;
        int cstart = (wid >> 2) * 64;
        #pragma unroll
        for (int cb = 0; cb < 64; cb += 32) {
            uint32_t dr[32];
            LDTM32(dr, tmem + cstart + cb);
            TC_WAIT_LD();
            #pragma unroll
            for (int j = 0; j < 32; j += 4) {
                int col = bn + cstart + cb + j;
                if (col >= Ntot) continue;
                float4 v = make_float4(__uint_as_float(dr[j]),     __uint_as_float(dr[j + 1]),
                                       __uint_as_float(dr[j + 2]), __uint_as_float(dr[j + 3]));
                if (epi == 1) {
                    float4 r = *(const float4*)(epi_ptr + (size_t)row * ldc + col);
                    v.x += r.x; v.y += r.y; v.z += r.z; v.w += r.w;
                } else if (epi == 2) {
                    v.x = softplusf(v.x + epi_ptr[col]);
                    v.y = softplusf(v.y + epi_ptr[col + 1]);
                    v.z = softplusf(v.z + epi_ptr[col + 2]);
                    v.w = softplusf(v.w + epi_ptr[col + 3]);
                }
                *(float4*)(C + (size_t)row * ldc + col) = v;
                if (epi == 3) {
                    size_t o = (size_t)row * XDBLW + col;
                    __nv_bfloat16 h0,h1,h2,h3,l0,l1,l2,l3;
                    split1(v.x,h0,l0); split1(v.y,h1,l1); split1(v.z,h2,l2); split1(v.w,h3,l3);
                    *(__nv_bfloat162*)(g_xdh + o)     = __halves2bfloat162(h0, h1);
                    *(__nv_bfloat162*)(g_xdh + o + 2) = __halves2bfloat162(h2, h3);
                    *(__nv_bfloat162*)(g_xdl + o)     = __halves2bfloat162(l0, l1);
                    *(__nv_bfloat162*)(g_xdl + o + 2) = __halves2bfloat162(l2, l3);
                }
            }
        }
    }
    TC_FENCE_BEFORE();
    __syncthreads();
    if (tid == 0) { MBAR_INVAL(sb + 8); MBAR_INVAL(sb + 16); MBAR_INVAL(sb + 24); }
    __syncthreads();
    if (wid == 0) TC_DEALLOC(tmem, 128);

#else   // ---------------- FFMA fallback (non-'a' target) ----------------
    float (*As)[128] = (float (*)[128])(smem);            // [16][128]
    float (*Bs)[128] = (float (*)[128])(smem + 8192);     // [16][128]
    int tx = tid & 15, ty = tid >> 4;

    float acc[8][8];
    #pragma unroll
    for (int i = 0; i < 8; i++)
        #pragma unroll
        for (int j = 0; j < 8; j++) acc[i][j] = 0.f;

    for (int k0 = 0; k0 < K; k0 += 16) {
        // A tile: 128 rows x 16 k; 8 elems/thread
        {
            int row = tid >> 1, koff = (tid & 1) * 8;
            uint4 vh = *(const uint4*)(Ah + (size_t)(bm + row) * lda + k0 + koff);
            uint4 vl = *(const uint4*)(Al + (size_t)(bm + row) * lda + k0 + koff);
            const __nv_bfloat162* ph = (const __nv_bfloat162*)&vh;
            const __nv_bfloat162* pl = (const __nv_bfloat162*)&vl;
            #pragma unroll
            for (int q = 0; q < 4; q++) {
                float2 fh = __bfloat1622float2(ph[q]);
                float2 fl = __bfloat1622float2(pl[q]);
                As[koff + q*2 + 0][row] = fh.x + fl.x;
                As[koff + q*2 + 1][row] = fh.y + fl.y;
            }
        }
        // B tile with N guard
        {
            int row = tid >> 1, koff = (tid & 1) * 8;
            uint4 vh = make_uint4(0,0,0,0), vl = make_uint4(0,0,0,0);
            if (bn + row < Ntot) {
                vh = *(const uint4*)(Bh + (size_t)(bn + row) * ldb + k0 + koff);
                vl = *(const uint4*)(Bl + (size_t)(bn + row) * ldb + k0 + koff);
            }
            const __nv_bfloat162* ph = (const __nv_bfloat162*)&vh;
            const __nv_bfloat162* pl = (const __nv_bfloat162*)&vl;
            #pragma unroll
            for (int q = 0; q < 4; q++) {
                float2 fh = __bfloat1622float2(ph[q]);
                float2 fl = __bfloat1622float2(pl[q]);
                Bs[koff + q*2 + 0][row] = fh.x + fl.x;
                Bs[koff + q*2 + 1][row] = fh.y + fl.y;
            }
        }
        __syncthreads();
        #pragma unroll
        for (int k = 0; k < 16; k++) {
            float ra[8], rb[8];
            *(float4*)(ra + 0) = *(const float4*)&As[k][ty * 8 + 0];
            *(float4*)(ra + 4) = *(const float4*)&As[k][ty * 8 + 4];
            *(float4*)(rb + 0) = *(const float4*)&Bs[k][tx * 8 + 0];
            *(float4*)(rb + 4) = *(const float4*)&Bs[k][tx * 8 + 4];
            #pragma unroll
            for (int i = 0; i < 8; i++)
                #pragma unroll
                for (int j = 0; j < 8; j++)
                    acc[i][j] = fmaf(ra[i], rb[j], acc[i][j]);
        }
        __syncthreads();
    }

    #pragma unroll
    for (int i = 0; i < 8; i++) {
        int row = bm + ty * 8 + i;
        #pragma unroll
        for (int j = 0; j < 8; j++) {
            int col = bn + tx * 8 + j;
            if (col < Ntot) {
                float v = acc[i][j];
                if (epi == 1) v += epi_ptr[(size_t)row * ldc + col];
                else if (epi == 2) v = softplusf(v + epi_ptr[col]);
                C[(size_t)row * ldc + col] = v;
                if (epi == 3) {
                    __nv_bfloat16 h, l;
                    split1(v, h, l);
                    g_xdh[(size_t)row * XDBLW + col] = h;
                    g_xdl[(size_t)row * XDBLW + col] = l;
                }
            }
        }
    }
#endif
}

// ================= causal depthwise conv (w=4) + bias + SiLU -> u + planes ======
__global__ void conv_silu_kernel(const float* __restrict__ cw,
                                 const float* __restrict__ cb)
{
    int idx = blockIdx.x * blockDim.x + threadIdx.x;   // ROWS*DINNER
    if (idx >= ROWS * DINNER) return;
    int d   = idx & (DINNER - 1);
    int row = idx >> 11;                                // b*LSEQ + l
    int l   = row & (LSEQ - 1);
    float acc = cb[d];
    #pragma unroll
    for (int j = 0; j < 4; j++) {
        int li = l - 3 + j;
        float v = (li >= 0) ? g_xz[(size_t)(row - 3 + j) * (2 * DINNER) + d] : 0.f;
        acc = fmaf(cw[d * 4 + j], v, acc);
    }
    float sig = 1.f / (1.f + __expf(-acc));
    float val = acc * sig;
    g_u[idx] = val;
    __nv_bfloat16 h, lo;
    split1(val, h, lo);
    g_uh[idx] = h;
    g_ul[idx] = lo;
}

// ================= selective scan (+skip D*u, gate silu(z)) -> ybar planes ======
__device__ __forceinline__ void scan_load(size_t r, int d,
    float4 (&b)[4], float4 (&c)[4], float& dl, float& uu, float& zz)
{
    dl = g_delta[r * DINNER + d];
    uu = g_u[r * DINNER + d];
    zz = g_xz[r * (2 * DINNER) + DINNER + d];
    const float* xr = g_xdbl + r * XDBLW;
    b[0] = *(const float4*)(xr + 64); b[1] = *(const float4*)(xr + 68);
    b[2] = *(const float4*)(xr + 72); b[3] = *(const float4*)(xr + 76);
    c[0] = *(const float4*)(xr + 80); c[1] = *(const float4*)(xr + 84);
    c[2] = *(const float4*)(xr + 88); c[3] = *(const float4*)(xr + 92);
}

__global__ void scan_kernel(const float* __restrict__ A_log,
                            const float* __restrict__ Dp)
{
    int gid = blockIdx.x * blockDim.x + threadIdx.x;   // 0..4095
    if (gid >= BATCH * DINNER) return;
    int b = gid >> 11;
    int d = gid & (DINNER - 1);

    float Av[DSTATE];
    #pragma unroll
    for (int s = 0; s < DSTATE; s++) Av[s] = -__expf(A_log[d * DSTATE + s]);
    float A0 = Av[0];
    bool fast = true;
    #pragma unroll
    for (int s = 0; s < DSTATE; s++) {
        float ideal = A0 * (float)(s + 1);
        if (fabsf(Av[s] - ideal) > 1e-4f * fabsf(ideal) + 1e-6f) fast = false;
    }
    float Dd = Dp[d];

    float h[DSTATE];
    #pragma unroll
    for (int s = 0; s < DSTATE; s++) h[s] = 0.f;

    size_t base = (size_t)b * LSEQ;

    float4 b0[4], c0[4], b1[4], c1[4];
    float dl0, uu0, zz0, dl1, uu1, zz1;
    scan_load(base + 0, d, b0, c0, dl0, uu0, zz0);
    scan_load(base + 1, d, b1, c1, dl1, uu1, zz1);

    for (int l = 0; l < LSEQ; l += 2) {
        {
            float cd = dl0, cu = uu0, cz = zz0;
            float Bv[16], Cv[16];
            *(float4*)(Bv+0)=b0[0]; *(float4*)(Bv+4)=b0[1]; *(float4*)(Bv+8)=b0[2]; *(float4*)(Bv+12)=b0[3];
            *(float4*)(Cv+0)=c0[0]; *(float4*)(Cv+4)=c0[1]; *(float4*)(Cv+8)=c0[2]; *(float4*)(Cv+12)=c0[3];
            if (l + 2 < LSEQ) scan_load(base + l + 2, d, b0, c0, dl0, uu0, zz0);
            float du = cd * cu;
            float y0 = 0.f, y1 = 0.f;
            if (fast) {
                float E = __expf(cd * A0), p = E;
                #pragma unroll
                for (int s = 0; s < DSTATE; s++) {
                    h[s] = fmaf(p, h[s], du * Bv[s]);
                    if (s & 1) y1 = fmaf(h[s], Cv[s], y1); else y0 = fmaf(h[s], Cv[s], y0);
                    p *= E;
                }
            } else {
                #pragma unroll
                for (int s = 0; s < DSTATE; s++) {
                    float dA = __expf(cd * Av[s]);
                    h[s] = fmaf(dA, h[s], du * Bv[s]);
                    if (s & 1) y1 = fmaf(h[s], Cv[s], y1); else y0 = fmaf(h[s], Cv[s], y0);
                }
            }
            float y = y0 + y1 + Dd * cu;
            float sig = 1.f / (1.f + __expf(-cz));
            float yv = y * (cz * sig);
            __nv_bfloat16 bh, blx;
            split1(yv, bh, blx);
            size_t o = (base + l) * DINNER + d;
            g_ybh[o] = bh; g_ybl[o] = blx;
        }
        {
            float cd = dl1, cu = uu1, cz = zz1;
            float Bv[16], Cv[16];
            *(float4*)(Bv+0)=b1[0]; *(float4*)(Bv+4)=b1[1]; *(float4*)(Bv+8)=b1[2]; *(float4*)(Bv+12)=b1[3];
            *(float4*)(Cv+0)=c1[0]; *(float4*)(Cv+4)=c1[1]; *(float4*)(Cv+8)=c1[2]; *(float4*)(Cv+12)=c1[3];
            if (l + 3 < LSEQ) scan_load(base + l + 3, d, b1, c1, dl1, uu1, zz1);
            float du = cd * cu;
            float y0 = 0.f, y1 = 0.f;
            if (fast) {
                float E = __expf(cd * A0), p = E;
                #pragma unroll
                for (int s = 0; s < DSTATE; s++) {
                    h[s] = fmaf(p, h[s], du * Bv[s]);
                    if (s & 1) y1 = fmaf(h[s], Cv[s], y1); else y0 = fmaf(h[s], Cv[s], y0);
                    p *= E;
                }
            } else {
                #pragma unroll
                for (int s = 0; s < DSTATE; s++) {
                    float dA = __expf(cd * Av[s]);
                    h[s] = fmaf(dA, h[s], du * Bv[s]);
                    if (s & 1) y1 = fmaf(h[s], Cv[s], y1); else y0 = fmaf(h[s], Cv[s], y0);
                }
            }
            float y = y0 + y1 + Dd * cu;
            float sig = 1.f / (1.f + __expf(-cz));
            float yv = y * (cz * sig);
            __nv_bfloat16 bh, blx;
            split1(yv, bh, blx);
            size_t o = (base + l + 1) * DINNER + d;
            g_ybh[o] = bh; g_ybl[o] = blx;
        }
    }
}

// ================= launch =================
extern "C" void kernel_launch(void* const* d_in, const int* in_sizes, int n_in,
                              void* d_out, int out_size)
{
    const float* x      = (const float*)d_in[0];
    const float* norm_w = (const float*)d_in[1];
    const float* norm_b = (const float*)d_in[2];
    const float* W_in   = (const float*)d_in[3];
    const float* conv_w = (const float*)d_in[4];
    const float* conv_b = (const float*)d_in[5];
    const float* W_x    = (const float*)d_in[6];
    const float* W_dt   = (const float*)d_in[7];
    const float* b_dt   = (const float*)d_in[8];
    const float* A_log  = (const float*)d_in[9];
    const float* Dp     = (const float*)d_in[10];
    const float* W_out  = (const float*)d_in[11];
    float* out = (float*)d_out;

    // allow >48KB dynamic smem for the GEMM (idempotent; not a stream op)
    cudaFuncSetAttribute(tc_gemm, cudaFuncAttributeMaxDynamicSharedMemorySize, GEMM_SMEM);

    // 0) weight conversions -> split planes
    {
        int n4;
        n4 = (2*DINNER*DMODEL) / 4; cvt_split<<<(n4 + 255) / 256, 256>>>(W_in, 0, n4);
        n4 = (XDBLW*DINNER) / 4;    cvt_split<<<(n4 + 255) / 256, 256>>>(W_x, 1, n4);
        n4 = (DINNER*DTRANK) / 4;   cvt_split<<<(n4 + 255) / 256, 256>>>(W_dt, 2, n4);
        n4 = (DMODEL*DINNER) / 4;   cvt_split<<<(n4 + 255) / 256, 256>>>(W_out, 3, n4);
    }

    // 1) LayerNorm -> xn planes
    ln_kernel<<<ROWS, 256>>>(x, norm_w, norm_b);

    // 2) in_proj: g_xz = xn @ W_in^T   (N=4096, K=1024)
    tc_gemm<<<dim3(32, 32), 256, GEMM_SMEM>>>(PL_XN, PL_WIN, CF_XZ, nullptr,
        4096, 1024, DMODEL, DMODEL, 2 * DINNER, 0, nullptr);

    // 3) conv + SiLU -> u (fp32 + planes)
    conv_silu_kernel<<<(ROWS * DINNER + 255) / 256, 256>>>(conv_w, conv_b);

    // 4) x_proj: g_xdbl = u @ W_x^T   (N=96, K=2048) + split planes
    tc_gemm<<<dim3(1, 32), 256, GEMM_SMEM>>>(PL_U, PL_WX, CF_XDBL, nullptr,
        96, 2048, DINNER, DINNER, XDBLW, 3, nullptr);

    // 5) dt_proj + softplus: g_delta = softplus(xdbl[:, :64] @ W_dt^T + b_dt)  (N=2048, K=64)
    tc_gemm<<<dim3(16, 32), 256, GEMM_SMEM>>>(PL_XD, PL_WDT, CF_DELTA, nullptr,
        2048, 64, XDBLW, DTRANK, DINNER, 2, b_dt);

    // 6) selective scan -> ybar planes
    scan_kernel<<<(BATCH * DINNER + 63) / 64, 64>>>(A_log, Dp);

    // 7) out_proj + residual: out = ybar @ W_out^T + x  (N=1024, K=2048)
    tc_gemm<<<dim3(8, 32), 256, GEMM_SMEM>>>(PL_YB, PL_WOUT, CF_EXT, out,
        1024, 2048, DINNER, DINNER, DMODEL, 1, x);
}

// round 12
// speedup vs baseline: 3.5570x; 2.3859x over previous
#include <cuda_runtime.h>
#include <cuda_bf16.h>
#include <stdint.h>
#include <math.h>

#define BATCH   2
#define LSEQ    2048
#define DMODEL  1024
#define DINNER  2048
#define DSTATE  16
#define DTRANK  64
#define XDBLW   (DTRANK + 2*DSTATE)   // 96
#define ROWS    (BATCH*LSEQ)          // 4096
#define EPSLN   1e-5f
#define NCHK    16
#define CLEN    (LSEQ/NCHK)           // 128

// ================= scratch (static device globals; no allocation) =================
__device__ float g_xz   [(size_t)ROWS * 2 * DINNER];    // 64 MB
__device__ float g_u    [(size_t)ROWS * DINNER];        // 32 MB
__device__ float g_xdbl [(size_t)ROWS * XDBLW];         // 1.5 MB
__device__ float g_delta[(size_t)ROWS * DINNER];        // 32 MB
// chunked-scan state
__device__ float g_hloc[(size_t)BATCH*DINNER*NCHK*DSTATE];   // 4 MB
__device__ float g_hin [(size_t)BATCH*DINNER*NCHK*DSTATE];   // 4 MB
__device__ float g_sumd[(size_t)BATCH*DINNER*NCHK];          // 256 KB
// split-bf16 planes (hi, lo)
__device__ __nv_bfloat16 g_xnh[(size_t)ROWS*DMODEL],  g_xnl[(size_t)ROWS*DMODEL];
__device__ __nv_bfloat16 g_uh [(size_t)ROWS*DINNER],  g_ul [(size_t)ROWS*DINNER];
__device__ __nv_bfloat16 g_xdh[(size_t)ROWS*XDBLW],   g_xdl[(size_t)ROWS*XDBLW];
__device__ __nv_bfloat16 g_ybh[(size_t)ROWS*DINNER],  g_ybl[(size_t)ROWS*DINNER];
__device__ __nv_bfloat16 g_winh[(size_t)2*DINNER*DMODEL], g_winl[(size_t)2*DINNER*DMODEL];
__device__ __nv_bfloat16 g_wxh [(size_t)XDBLW*DINNER],    g_wxl [(size_t)XDBLW*DINNER];
__device__ __nv_bfloat16 g_wdth[(size_t)DINNER*DTRANK],   g_wdtl[(size_t)DINNER*DTRANK];
__device__ __nv_bfloat16 g_wouth[(size_t)DMODEL*DINNER],  g_woutl[(size_t)DMODEL*DINNER];

#define PL_XN 0
#define PL_U 1
#define PL_XD 2
#define PL_YB 3
#define PL_WIN 4
#define PL_WX 5
#define PL_WDT 6
#define PL_WOUT 7
__device__ __forceinline__ void sel_planes(int s, const __nv_bfloat16*& h, const __nv_bfloat16*& l) {
    switch (s) {
        case PL_XN:  h = g_xnh;  l = g_xnl;  break;
        case PL_U:   h = g_uh;   l = g_ul;   break;
        case PL_XD:  h = g_xdh;  l = g_xdl;  break;
        case PL_YB:  h = g_ybh;  l = g_ybl;  break;
        case PL_WIN: h = g_winh; l = g_winl; break;
        case PL_WX:  h = g_wxh;  l = g_wxl;  break;
        case PL_WDT: h = g_wdth; l = g_wdtl; break;
        default:     h = g_wouth;l = g_woutl;break;
    }
}
#define CF_XZ 0
#define CF_XDBL 1
#define CF_DELTA 2
#define CF_EXT (-1)

// Arch-specific (sm_103a) feature gate: tcgen05 only exists on the 'a' target.
#if defined(__CUDA_ARCH__) && (defined(__CUDA_ARCH_FEAT_SM103_ALL) || defined(__CUDA_ARCH_FEAT_SM100_ALL))
#define HAS_TCGEN05 1
#else
#define HAS_TCGEN05 0
#endif

// ================= helpers =================
__device__ __forceinline__ float softplusf(float x) {
    return (x > 20.f) ? x : log1pf(__expf(x));
}
__device__ __forceinline__ void split1(float v, __nv_bfloat16& h, __nv_bfloat16& l) {
    h = __float2bfloat16(v);
    l = __float2bfloat16(v - __bfloat162float(h));
}

#if HAS_TCGEN05
__device__ __forceinline__ uint32_t smem_u32(const void* p) {
    uint32_t a;
    asm("{ .reg .u64 t; cvta.to.shared.u64 t, %1; cvt.u32.u64 %0, t; }" : "=r"(a) : "l"(p));
    return a;
}
__device__ __forceinline__ uint32_t elect1() {
    uint32_t p;
    asm volatile("{\n\t.reg .pred p;\n\telect.sync _|p, 0xFFFFFFFF;\n\tselp.b32 %0, 1, 0, p;\n\t}" : "=r"(p));
    return p;
}
__device__ __forceinline__ uint64_t mkdesc(uint32_t addr) {
    const uint64_t base = (uint64_t(2) << 61) | (uint64_t(1) << 46)
                        | (uint64_t(64) << 32) | (uint64_t(1) << 16);   // SW128, v1, SBO=64, LBO=1
    return base | ((uint64_t)(addr >> 4) & 0x3FFF);
}
__device__ __forceinline__ void mma_bf16_ss(uint32_t d, uint64_t da, uint64_t db, uint32_t idesc, uint32_t en) {
    asm volatile("{\n\t.reg .pred p;\n\tsetp.ne.u32 p, %5, 0;\n\t"
        "tcgen05.mma.cta_group::1.kind::f16 [%0], %1, %2, %3, {%4, %4, %4, %4}, p;\n\t}"
        :: "r"(d), "l"(da), "l"(db), "r"(idesc), "r"(0u), "r"(en) : "memory");
}
#define TC_ALLOC(sm, n)   asm volatile("tcgen05.alloc.cta_group::1.sync.aligned.shared::cta.b32 [%0], %1;" :: "r"(sm), "r"(n) : "memory")
#define TC_RELQ()         asm volatile("tcgen05.relinquish_alloc_permit.cta_group::1.sync.aligned;")
#define TC_DEALLOC(t, n)  asm volatile("tcgen05.dealloc.cta_group::1.sync.aligned.b32 %0, %1;" :: "r"(t), "r"(n))
#define TC_COMMIT(mb)     asm volatile("tcgen05.commit.cta_group::1.mbarrier::arrive::one.shared::cluster.b64 [%0];" :: "r"(mb) : "memory")
#define TC_WAIT_LD()      asm volatile("tcgen05.wait::ld.sync.aligned;" ::: "memory")
#define TC_FENCE_AFTER()  asm volatile("tcgen05.fence::after_thread_sync;" ::: "memory")
#define TC_FENCE_BEFORE() asm volatile("tcgen05.fence::before_thread_sync;" ::: "memory")
#define FENCE_ASYNC()     asm volatile("fence.proxy.async.shared::cta;" ::: "memory")
#define MBAR_INIT(mb, c)  asm volatile("mbarrier.init.shared.b64 [%0], %1;" :: "r"(mb), "r"(c) : "memory")
#define MBAR_INVAL(mb)    asm volatile("mbarrier.inval.shared.b64 [%0];" :: "r"(mb) : "memory")
#define MBAR_WAIT(mb, ph) do { \
    uint32_t _m = (mb), _p = (ph), _done; \
    asm volatile("{\n\t.reg .pred p;\n\tmbarrier.try_wait.parity.acquire.cta.shared::cta.b64 p, [%1], %2;\n\tselp.b32 %0, 1, 0, p;\n\t}" \
        : "=r"(_done) : "r"(_m), "r"(_p) : "memory"); \
    if (!_done) { \
        asm volatile("{\n\t.reg .pred P1;\n\tWL%=:\n\tmbarrier.try_wait.parity.acquire.cta.shared::cta.b64 P1, [%0], %1, 0x989680;\n\t@P1 bra.uni WD%=;\n\tbra.uni WL%=;\n\tWD%=:\n\t}" \
            :: "r"(_m), "r"(_p) : "memory"); \
    } \
} while (0)
#define LDTM32(r, addr) \
    asm volatile("tcgen05.ld.sync.aligned.32x32b.x32.b32 " \
        "{%0, %1, %2, %3, %4, %5, %6, %7, %8, %9, %10, %11, %12, %13, %14, %15, " \
        " %16, %17, %18, %19, %20, %21, %22, %23, %24, %25, %26, %27, %28, %29, %30, %31}, [%32];" \
        : "=r"((r)[0]),  "=r"((r)[1]),  "=r"((r)[2]),  "=r"((r)[3]), \
          "=r"((r)[4]),  "=r"((r)[5]),  "=r"((r)[6]),  "=r"((r)[7]), \
          "=r"((r)[8]),  "=r"((r)[9]),  "=r"((r)[10]), "=r"((r)[11]), \
          "=r"((r)[12]), "=r"((r)[13]), "=r"((r)[14]), "=r"((r)[15]), \
          "=r"((r)[16]), "=r"((r)[17]), "=r"((r)[18]), "=r"((r)[19]), \
          "=r"((r)[20]), "=r"((r)[21]), "=r"((r)[22]), "=r"((r)[23]), \
          "=r"((r)[24]), "=r"((r)[25]), "=r"((r)[26]), "=r"((r)[27]), \
          "=r"((r)[28]), "=r"((r)[29]), "=r"((r)[30]), "=r"((r)[31]) \
        : "r"(addr))
#define SW128(x) ((x) ^ (((x) >> 3) & 0x70))
#endif  // HAS_TCGEN05

// ================= LayerNorm -> split planes =================
__global__ void ln_kernel(const float* __restrict__ x,
                          const float* __restrict__ w,
                          const float* __restrict__ b)
{
    int row = blockIdx.x;
    int tid = threadIdx.x;                 // 256 threads, 4 floats each
    const float4* xr = (const float4*)(x + (size_t)row * DMODEL);
    float4 v = xr[tid];
    float s  = v.x + v.y + v.z + v.w;
    float sq = v.x*v.x + v.y*v.y + v.z*v.z + v.w*v.w;
    #pragma unroll
    for (int o = 16; o > 0; o >>= 1) {
        s  += __shfl_down_sync(0xffffffffu, s,  o);
        sq += __shfl_down_sync(0xffffffffu, sq, o);
    }
    __shared__ float ss[8], sqs[8];
    int wid = tid >> 5, lid = tid & 31;
    if (lid == 0) { ss[wid] = s; sqs[wid] = sq; }
    __syncthreads();
    __shared__ float s_mu, s_rstd;
    if (tid == 0) {
        float ts = 0.f, tq = 0.f;
        #pragma unroll
        for (int i = 0; i < 8; i++) { ts += ss[i]; tq += sqs[i]; }
        float mu  = ts * (1.f / DMODEL);
        float var = tq * (1.f / DMODEL) - mu * mu;
        s_mu = mu; s_rstd = rsqrtf(var + EPSLN);
    }
    __syncthreads();
    float mu = s_mu, rstd = s_rstd;
    float4 w4 = ((const float4*)w)[tid];
    float4 b4 = ((const float4*)b)[tid];
    float o0 = (v.x - mu) * rstd * w4.x + b4.x;
    float o1 = (v.y - mu) * rstd * w4.y + b4.y;
    float o2 = (v.z - mu) * rstd * w4.z + b4.z;
    float o3 = (v.w - mu) * rstd * w4.w + b4.w;
    __nv_bfloat16 h0,h1,h2,h3,l0,l1,l2,l3;
    split1(o0,h0,l0); split1(o1,h1,l1); split1(o2,h2,l2); split1(o3,h3,l3);
    size_t o = (size_t)row * DMODEL + tid * 4;
    *(__nv_bfloat162*)(g_xnh + o)     = __halves2bfloat162(h0, h1);
    *(__nv_bfloat162*)(g_xnh + o + 2) = __halves2bfloat162(h2, h3);
    *(__nv_bfloat162*)(g_xnl + o)     = __halves2bfloat162(l0, l1);
    *(__nv_bfloat162*)(g_xnl + o + 2) = __halves2bfloat162(l2, l3);
}

// ================= fp32 -> split bf16 weight conversion =================
__global__ void cvt_split(const float* __restrict__ src, int dsel, int n4)
{
    __nv_bfloat16 *dh, *dl;
    switch (dsel) {
        case 0:  dh = g_winh;  dl = g_winl;  break;
        case 1:  dh = g_wxh;   dl = g_wxl;   break;
        case 2:  dh = g_wdth;  dl = g_wdtl;  break;
        default: dh = g_wouth; dl = g_woutl; break;
    }
    int i = blockIdx.x * blockDim.x + threadIdx.x;
    if (i >= n4) return;
    float4 v = ((const float4*)src)[i];
    __nv_bfloat16 h0,h1,h2,h3,l0,l1,l2,l3;
    split1(v.x,h0,l0); split1(v.y,h1,l1); split1(v.z,h2,l2); split1(v.w,h3,l3);
    size_t o = (size_t)i * 4;
    *(__nv_bfloat162*)(dh + o)     = __halves2bfloat162(h0, h1);
    *(__nv_bfloat162*)(dh + o + 2) = __halves2bfloat162(h2, h3);
    *(__nv_bfloat162*)(dl + o)     = __halves2bfloat162(l0, l1);
    *(__nv_bfloat162*)(dl + o + 2) = __halves2bfloat162(l2, l3);
}

// ================= split-bf16 NT GEMM (tcgen05 on sm_103a; FFMA fallback) ========
#define KC       64
#define PLANE_B  16384           // 128 rows * 128 bytes
#define STAGE_B  (4*PLANE_B)     // Ahi, Alo, Bhi, Blo
#define SMD      1024
#define GEMM_SMEM (SMD + 2*STAGE_B)   // 132096

#if HAS_TCGEN05
__device__ __forceinline__ void load_stage(char* smem, int s, int c,
    const __nv_bfloat16* __restrict__ Ah, const __nv_bfloat16* __restrict__ Al,
    const __nv_bfloat16* __restrict__ Bh, const __nv_bfloat16* __restrict__ Bl,
    int lda, int ldb, int bm, int bn, int Ntot, int tid)
{
    char* base = smem + SMD + s * STAGE_B;
    int kb = c * KC;
    #pragma unroll
    for (int i = 0; i < 4; i++) {
        int idx = tid + i * 256;
        int rowi = idx >> 3, u16 = idx & 7;
        uint32_t off = SW128((uint32_t)(rowi * 128 + u16 * 16));
        size_t aoff = (size_t)(bm + rowi) * lda + kb + u16 * 8;
        *(uint4*)(base + off)           = *(const uint4*)(Ah + aoff);
        *(uint4*)(base + PLANE_B + off) = *(const uint4*)(Al + aoff);
        uint4 vh = make_uint4(0,0,0,0), vl = make_uint4(0,0,0,0);
        if (bn + rowi < Ntot) {
            size_t boff = (size_t)(bn + rowi) * ldb + kb + u16 * 8;
            vh = *(const uint4*)(Bh + boff);
            vl = *(const uint4*)(Bl + boff);
        }
        *(uint4*)(base + 2*PLANE_B + off) = vh;
        *(uint4*)(base + 3*PLANE_B + off) = vl;
    }
}
#endif

__global__ __launch_bounds__(256)
void tc_gemm(int a_sel, int b_sel, int c_sel, float* __restrict__ Cext,
             int Ntot, int K, int lda, int ldb, int ldc,
             int epi, const float* __restrict__ epi_ptr)
{
    extern __shared__ char smem[];
    const __nv_bfloat16 *Ah, *Al, *Bh, *Bl;
    sel_planes(a_sel, Ah, Al);
    sel_planes(b_sel, Bh, Bl);
    float* C;
    switch (c_sel) {
        case CF_XZ:    C = g_xz;    break;
        case CF_XDBL:  C = g_xdbl;  break;
        case CF_DELTA: C = g_delta; break;
        default:       C = Cext;    break;
    }
    int tid = threadIdx.x;
    int bm = blockIdx.y * 128;
    int bn = blockIdx.x * 128;

#if HAS_TCGEN05
    uint32_t sb = smem_u32(smem);
    int wid = tid >> 5, lid = tid & 31;

    if (wid == 0) { TC_ALLOC(sb + 0, 128); TC_RELQ(); }
    if (tid == 0) { MBAR_INIT(sb + 8, 1); MBAR_INIT(sb + 16, 1); MBAR_INIT(sb + 24, 1); }
    __syncthreads();
    uint32_t tmem;
    asm volatile("ld.shared.b32 %0, [%1];" : "=r"(tmem) : "r"(sb + 0));

    const uint32_t idesc = (1u << 4) | (1u << 7) | (1u << 10)
                         | (16u << 17) | (8u << 24);   // F32 acc, bf16 a/b, N=128, M=128
    int NC = K / KC;

    load_stage(smem, 0, 0, Ah, Al, Bh, Bl, lda, ldb, bm, bn, Ntot, tid);
    FENCE_ASYNC();
    __syncthreads();

    int wcnt0 = 0, wcnt1 = 0;
    for (int c = 0; c < NC; c++) {
        int s = c & 1;
        if (wid == 0 && elect1()) {
            uint32_t stg = sb + SMD + s * STAGE_B;
            uint64_t dAh = mkdesc(stg), dAl = mkdesc(stg + PLANE_B);
            uint64_t dBh = mkdesc(stg + 2 * PLANE_B), dBl = mkdesc(stg + 3 * PLANE_B);
            #pragma unroll
            for (int k = 0; k < 4; k++) {       // K=16 per MMA, desc += 2 per step
                mma_bf16_ss(tmem, dAh + k*2, dBh + k*2, idesc, (c == 0 && k == 0) ? 0u : 1u);
                mma_bf16_ss(tmem, dAl + k*2, dBh + k*2, idesc, 1u);
                mma_bf16_ss(tmem, dAh + k*2, dBl + k*2, idesc, 1u);
            }
            TC_COMMIT(sb + 8 + 8 * s);
        }
        if (c + 1 < NC) {
            int t = s ^ 1;
            if (c >= 1) {
                int ph = ((t == 0) ? wcnt0 : wcnt1) & 1;
                MBAR_WAIT(sb + 8 + 8 * t, ph);
                if (t == 0) wcnt0++; else wcnt1++;
            }
            load_stage(smem, t, c + 1, Ah, Al, Bh, Bl, lda, ldb, bm, bn, Ntot, tid);
            FENCE_ASYNC();
            __syncthreads();
        }
    }
    if (wid == 0 && elect1()) TC_COMMIT(sb + 24);
    MBAR_WAIT(sb + 24, 0);
    TC_FENCE_AFTER();

    // epilogue: warps 0-3 cols [0,64), warps 4-7 cols [64,128); rows by subpartition
    {
        int sub = wid & 3;
        int row = bm + sub * 32 + lid;
        int cstart = (wid >> 2) * 64;
        #pragma unroll
        for (int cb = 0; cb < 64; cb += 32) {
            uint32_t dr[32];
            LDTM32(dr, tmem + cstart + cb);
            TC_WAIT_LD();
            #pragma unroll
            for (int j = 0; j < 32; j += 4) {
                int col = bn + cstart + cb + j;
                if (col >= Ntot) continue;
                float4 v = make_float4(__uint_as_float(dr[j]),     __uint_as_float(dr[j + 1]),
                                       __uint_as_float(dr[j + 2]), __uint_as_float(dr[j + 3]));
                if (epi == 1) {
                    float4 r = *(const float4*)(epi_ptr + (size_t)row * ldc + col);
                    v.x += r.x; v.y += r.y; v.z += r.z; v.w += r.w;
                } else if (epi == 2) {
                    v.x = softplusf(v.x + epi_ptr[col]);
                    v.y = softplusf(v.y + epi_ptr[col + 1]);
                    v.z = softplusf(v.z + epi_ptr[col + 2]);
                    v.w = softplusf(v.w + epi_ptr[col + 3]);
                }
                *(float4*)(C + (size_t)row * ldc + col) = v;
                if (epi == 3) {
                    size_t o = (size_t)row * XDBLW + col;
                    __nv_bfloat16 h0,h1,h2,h3,l0,l1,l2,l3;
                    split1(v.x,h0,l0); split1(v.y,h1,l1); split1(v.z,h2,l2); split1(v.w,h3,l3);
                    *(__nv_bfloat162*)(g_xdh + o)     = __halves2bfloat162(h0, h1);
                    *(__nv_bfloat162*)(g_xdh + o + 2) = __halves2bfloat162(h2, h3);
                    *(__nv_bfloat162*)(g_xdl + o)     = __halves2bfloat162(l0, l1);
                    *(__nv_bfloat162*)(g_xdl + o + 2) = __halves2bfloat162(l2, l3);
                }
            }
        }
    }
    TC_FENCE_BEFORE();
    __syncthreads();
    if (tid == 0) { MBAR_INVAL(sb + 8); MBAR_INVAL(sb + 16); MBAR_INVAL(sb + 24); }
    __syncthreads();
    if (wid == 0) TC_DEALLOC(tmem, 128);

#else   // ---------------- FFMA fallback (non-'a' target) ----------------
    float (*As)[128] = (float (*)[128])(smem);            // [16][128]
    float (*Bs)[128] = (float (*)[128])(smem + 8192);     // [16][128]
    int tx = tid & 15, ty = tid >> 4;

    float acc[8][8];
    #pragma unroll
    for (int i = 0; i < 8; i++)
        #pragma unroll
        for (int j = 0; j < 8; j++) acc[i][j] = 0.f;

    for (int k0 = 0; k0 < K; k0 += 16) {
        {
            int row = tid >> 1, koff = (tid & 1) * 8;
            uint4 vh = *(const uint4*)(Ah + (size_t)(bm + row) * lda + k0 + koff);
            uint4 vl = *(const uint4*)(Al + (size_t)(bm + row) * lda + k0 + koff);
            const __nv_bfloat162* ph = (const __nv_bfloat162*)&vh;
            const __nv_bfloat162* pl = (const __nv_bfloat162*)&vl;
            #pragma unroll
            for (int q = 0; q < 4; q++) {
                float2 fh = __bfloat1622float2(ph[q]);
                float2 fl = __bfloat1622float2(pl[q]);
                As[koff + q*2 + 0][row] = fh.x + fl.x;
                As[koff + q*2 + 1][row] = fh.y + fl.y;
            }
        }
        {
            int row = tid >> 1, koff = (tid & 1) * 8;
            uint4 vh = make_uint4(0,0,0,0), vl = make_uint4(0,0,0,0);
            if (bn + row < Ntot) {
                vh = *(const uint4*)(Bh + (size_t)(bn + row) * ldb + k0 + koff);
                vl = *(const uint4*)(Bl + (size_t)(bn + row) * ldb + k0 + koff);
            }
            const __nv_bfloat162* ph = (const __nv_bfloat162*)&vh;
            const __nv_bfloat162* pl = (const __nv_bfloat162*)&vl;
            #pragma unroll
            for (int q = 0; q < 4; q++) {
                float2 fh = __bfloat1622float2(ph[q]);
                float2 fl = __bfloat1622float2(pl[q]);
                Bs[koff + q*2 + 0][row] = fh.x + fl.x;
                Bs[koff + q*2 + 1][row] = fh.y + fl.y;
            }
        }
        __syncthreads();
        #pragma unroll
        for (int k = 0; k < 16; k++) {
            float ra[8], rb[8];
            *(float4*)(ra + 0) = *(const float4*)&As[k][ty * 8 + 0];
            *(float4*)(ra + 4) = *(const float4*)&As[k][ty * 8 + 4];
            *(float4*)(rb + 0) = *(const float4*)&Bs[k][tx * 8 + 0];
            *(float4*)(rb + 4) = *(const float4*)&Bs[k][tx * 8 + 4];
            #pragma unroll
            for (int i = 0; i < 8; i++)
                #pragma unroll
                for (int j = 0; j < 8; j++)
                    acc[i][j] = fmaf(ra[i], rb[j], acc[i][j]);
        }
        __syncthreads();
    }

    #pragma unroll
    for (int i = 0; i < 8; i++) {
        int row = bm + ty * 8 + i;
        #pragma unroll
        for (int j = 0; j < 8; j++) {
            int col = bn + tx * 8 + j;
            if (col < Ntot) {
                float v = acc[i][j];
                if (epi == 1) v += epi_ptr[(size_t)row * ldc + col];
                else if (epi == 2) v = softplusf(v + epi_ptr[col]);
                C[(size_t)row * ldc + col] = v;
                if (epi == 3) {
                    __nv_bfloat16 h, l;
                    split1(v, h, l);
                    g_xdh[(size_t)row * XDBLW + col] = h;
                    g_xdl[(size_t)row * XDBLW + col] = l;
                }
            }
        }
    }
#endif
}

// ================= causal depthwise conv (w=4) + bias + SiLU -> u + planes ======
__global__ void conv_silu_kernel(const float* __restrict__ cw,
                                 const float* __restrict__ cb)
{
    int idx = blockIdx.x * blockDim.x + threadIdx.x;   // ROWS*DINNER
    if (idx >= ROWS * DINNER) return;
    int d   = idx & (DINNER - 1);
    int row = idx >> 11;                                // b*LSEQ + l
    int l   = row & (LSEQ - 1);
    float acc = cb[d];
    #pragma unroll
    for (int j = 0; j < 4; j++) {
        int li = l - 3 + j;
        float v = (li >= 0) ? g_xz[(size_t)(row - 3 + j) * (2 * DINNER) + d] : 0.f;
        acc = fmaf(cw[d * 4 + j], v, acc);
    }
    float sig = 1.f / (1.f + __expf(-acc));
    float val = acc * sig;
    g_u[idx] = val;
    __nv_bfloat16 h, lo;
    split1(val, h, lo);
    g_uh[idx] = h;
    g_ul[idx] = lo;
}

// ================= chunked selective scan =================
// identity: prod_l exp(delta_l * A_s) = exp(A_s * sum_l delta_l)  (A_s const per (d,s))
__device__ __forceinline__ void load_A(const float* __restrict__ A_log, int d,
                                       float (&Av)[DSTATE], float& A0, bool& fast)
{
    #pragma unroll
    for (int s = 0; s < DSTATE; s++) Av[s] = -__expf(A_log[d * DSTATE + s]);
    A0 = Av[0];
    fast = true;
    #pragma unroll
    for (int s = 0; s < DSTATE; s++) {
        float ideal = A0 * (float)(s + 1);
        if (fabsf(Av[s] - ideal) > 1e-4f * fabsf(ideal) + 1e-6f) fast = false;
    }
}

// pass 1: per-(b,d,chunk) local scan from h=0 -> h_loc, sum(delta)
__global__ void scan_pass1(const float* __restrict__ A_log)
{
    int gid = blockIdx.x * blockDim.x + threadIdx.x;   // (c*BATCH + b)*DINNER + d
    if (gid >= BATCH * DINNER * NCHK) return;
    int d = gid & (DINNER - 1);
    int b = (gid >> 11) & (BATCH - 1);
    int c = gid >> 12;

    float Av[DSTATE], A0; bool fast;
    load_A(A_log, d, Av, A0, fast);

    float h[DSTATE];
    #pragma unroll
    for (int s = 0; s < DSTATE; s++) h[s] = 0.f;
    float sumd = 0.f;

    size_t row = (size_t)b * LSEQ + (size_t)c * CLEN;
    #pragma unroll 2
    for (int l = 0; l < CLEN; l++, row++) {
        float dlt = g_delta[row * DINNER + d];
        float uu  = g_u[row * DINNER + d];
        const float* xr = g_xdbl + row * XDBLW;
        float Bv[16];
        *(float4*)(Bv + 0)  = *(const float4*)(xr + 64);
        *(float4*)(Bv + 4)  = *(const float4*)(xr + 68);
        *(float4*)(Bv + 8)  = *(const float4*)(xr + 72);
        *(float4*)(Bv + 12) = *(const float4*)(xr + 76);
        sumd += dlt;
        float du = dlt * uu;
        if (fast) {
            float E = __expf(dlt * A0), p = E;
            #pragma unroll
            for (int s = 0; s < DSTATE; s++) { h[s] = fmaf(p, h[s], du * Bv[s]); p *= E; }
        } else {
            #pragma unroll
            for (int s = 0; s < DSTATE; s++) {
                float dA = __expf(dlt * Av[s]);
                h[s] = fmaf(dA, h[s], du * Bv[s]);
            }
        }
    }
    size_t o = (size_t)gid * DSTATE;
    #pragma unroll
    for (int s = 0; s < DSTATE; s += 4)
        *(float4*)(g_hloc + o + s) = make_float4(h[s], h[s+1], h[s+2], h[s+3]);
    g_sumd[gid] = sumd;
}

// combine: per-(b,d) serial over chunks -> h_in per chunk
__global__ void scan_combine(const float* __restrict__ A_log)
{
    int gid = blockIdx.x * blockDim.x + threadIdx.x;   // b*DINNER + d
    if (gid >= BATCH * DINNER) return;
    int d = gid & (DINNER - 1);
    int b = gid >> 11;

    float Av[DSTATE], A0; bool fast;
    load_A(A_log, d, Av, A0, fast);

    float hin[DSTATE];
    #pragma unroll
    for (int s = 0; s < DSTATE; s++) hin[s] = 0.f;

    for (int c = 0; c < NCHK; c++) {
        size_t idx = ((size_t)c * BATCH + b) * DINNER + d;
        size_t o = idx * DSTATE;
        #pragma unroll
        for (int s = 0; s < DSTATE; s += 4)
            *(float4*)(g_hin + o + s) = make_float4(hin[s], hin[s+1], hin[s+2], hin[s+3]);
        if (c + 1 < NCHK) {
            float sd = g_sumd[idx];
            float hl[DSTATE];
            #pragma unroll
            for (int s = 0; s < DSTATE; s += 4)
                *(float4*)(hl + s) = *(const float4*)(g_hloc + o + s);
            if (fast) {
                float E = __expf(A0 * sd), p = E;
                #pragma unroll
                for (int s = 0; s < DSTATE; s++) { hin[s] = fmaf(p, hin[s], hl[s]); p *= E; }
            } else {
                #pragma unroll
                for (int s = 0; s < DSTATE; s++)
                    hin[s] = fmaf(__expf(Av[s] * sd), hin[s], hl[s]);
            }
        }
    }
}

// pass 2: per-(b,d,chunk) re-scan from h_in, emit gated outputs -> ybar planes
__global__ void scan_pass2(const float* __restrict__ A_log,
                           const float* __restrict__ Dp)
{
    int gid = blockIdx.x * blockDim.x + threadIdx.x;
    if (gid >= BATCH * DINNER * NCHK) return;
    int d = gid & (DINNER - 1);
    int b = (gid >> 11) & (BATCH - 1);
    int c = gid >> 12;

    float Av[DSTATE], A0; bool fast;
    load_A(A_log, d, Av, A0, fast);
    float Dd = Dp[d];

    float h[DSTATE];
    size_t o = (size_t)gid * DSTATE;
    #pragma unroll
    for (int s = 0; s < DSTATE; s += 4)
        *(float4*)(h + s) = *(const float4*)(g_hin + o + s);

    size_t row = (size_t)b * LSEQ + (size_t)c * CLEN;
    #pragma unroll 2
    for (int l = 0; l < CLEN; l++, row++) {
        float dlt = g_delta[row * DINNER + d];
        float uu  = g_u[row * DINNER + d];
        float zz  = g_xz[row * (2 * DINNER) + DINNER + d];
        const float* xr = g_xdbl + row * XDBLW;
        float Bv[16], Cv[16];
        *(float4*)(Bv + 0)  = *(const float4*)(xr + 64);
        *(float4*)(Bv + 4)  = *(const float4*)(xr + 68);
        *(float4*)(Bv + 8)  = *(const float4*)(xr + 72);
        *(float4*)(Bv + 12) = *(const float4*)(xr + 76);
        *(float4*)(Cv + 0)  = *(const float4*)(xr + 80);
        *(float4*)(Cv + 4)  = *(const float4*)(xr + 84);
        *(float4*)(Cv + 8)  = *(const float4*)(xr + 88);
        *(float4*)(Cv + 12) = *(const float4*)(xr + 92);
        float du = dlt * uu;
        float y0 = 0.f, y1 = 0.f;
        if (fast) {
            float E = __expf(dlt * A0), p = E;
            #pragma unroll
            for (int s = 0; s < DSTATE; s++) {
                h[s] = fmaf(p, h[s], du * Bv[s]);
                if (s & 1) y1 = fmaf(h[s], Cv[s], y1); else y0 = fmaf(h[s], Cv[s], y0);
                p *= E;
            }
        } else {
            #pragma unroll
            for (int s = 0; s < DSTATE; s++) {
                float dA = __expf(dlt * Av[s]);
                h[s] = fmaf(dA, h[s], du * Bv[s]);
                if (s & 1) y1 = fmaf(h[s], Cv[s], y1); else y0 = fmaf(h[s], Cv[s], y0);
            }
        }
        float y = y0 + y1 + Dd * uu;
        float sig = 1.f / (1.f + __expf(-zz));
        float yv = y * (zz * sig);
        __nv_bfloat16 bh, bl;
        split1(yv, bh, bl);
        size_t oo = row * DINNER + d;
        g_ybh[oo] = bh;
        g_ybl[oo] = bl;
    }
}

// ================= launch =================
extern "C" void kernel_launch(void* const* d_in, const int* in_sizes, int n_in,
                              void* d_out, int out_size)
{
    const float* x      = (const float*)d_in[0];
    const float* norm_w = (const float*)d_in[1];
    const float* norm_b = (const float*)d_in[2];
    const float* W_in   = (const float*)d_in[3];
    const float* conv_w = (const float*)d_in[4];
    const float* conv_b = (const float*)d_in[5];
    const float* W_x    = (const float*)d_in[6];
    const float* W_dt   = (const float*)d_in[7];
    const float* b_dt   = (const float*)d_in[8];
    const float* A_log  = (const float*)d_in[9];
    const float* Dp     = (const float*)d_in[10];
    const float* W_out  = (const float*)d_in[11];
    float* out = (float*)d_out;

    cudaFuncSetAttribute(tc_gemm, cudaFuncAttributeMaxDynamicSharedMemorySize, GEMM_SMEM);

    // 0) weight conversions -> split planes
    {
        int n4;
        n4 = (2*DINNER*DMODEL) / 4; cvt_split<<<(n4 + 255) / 256, 256>>>(W_in, 0, n4);
        n4 = (XDBLW*DINNER) / 4;    cvt_split<<<(n4 + 255) / 256, 256>>>(W_x, 1, n4);
        n4 = (DINNER*DTRANK) / 4;   cvt_split<<<(n4 + 255) / 256, 256>>>(W_dt, 2, n4);
        n4 = (DMODEL*DINNER) / 4;   cvt_split<<<(n4 + 255) / 256, 256>>>(W_out, 3, n4);
    }

    // 1) LayerNorm -> xn planes
    ln_kernel<<<ROWS, 256>>>(x, norm_w, norm_b);

    // 2) in_proj: g_xz = xn @ W_in^T   (N=4096, K=1024)
    tc_gemm<<<dim3(32, 32), 256, GEMM_SMEM>>>(PL_XN, PL_WIN, CF_XZ, nullptr,
        4096, 1024, DMODEL, DMODEL, 2 * DINNER, 0, nullptr);

    // 3) conv + SiLU -> u (fp32 + planes)
    conv_silu_kernel<<<(ROWS * DINNER + 255) / 256, 256>>>(conv_w, conv_b);

    // 4) x_proj: g_xdbl = u @ W_x^T   (N=96, K=2048) + split planes
    tc_gemm<<<dim3(1, 32), 256, GEMM_SMEM>>>(PL_U, PL_WX, CF_XDBL, nullptr,
        96, 2048, DINNER, DINNER, XDBLW, 3, nullptr);

    // 5) dt_proj + softplus: g_delta = softplus(xdbl[:, :64] @ W_dt^T + b_dt)  (N=2048, K=64)
    tc_gemm<<<dim3(16, 32), 256, GEMM_SMEM>>>(PL_XD, PL_WDT, CF_DELTA, nullptr,
        2048, 64, XDBLW, DTRANK, DINNER, 2, b_dt);

    // 6) chunked scan: pass1 -> combine -> pass2
    scan_pass1<<<(BATCH * DINNER * NCHK + 255) / 256, 256>>>(A_log);
    scan_combine<<<(BATCH * DINNER + 255) / 256, 256>>>(A_log);
    scan_pass2<<<(BATCH * DINNER * NCHK + 255) / 256, 256>>>(A_log, Dp);

    // 7) out_proj + residual: out = ybar @ W_out^T + x  (N=1024, K=2048)
    tc_gemm<<<dim3(8, 32), 256, GEMM_SMEM>>>(PL_YB, PL_WOUT, CF_EXT, out,
        1024, 2048, DINNER, DINNER, DMODEL, 1, x);
}

// round 15
// speedup vs baseline: 5.7861x; 1.6267x over previous
#include <cuda_runtime.h>
#include <cuda_bf16.h>
#include <stdint.h>
#include <math.h>

#define BATCH   2
#define LSEQ    2048
#define DMODEL  1024
#define DINNER  2048
#define DSTATE  16
#define DTRANK  64
#define XDBLW   (DTRANK + 2*DSTATE)   // 96
#define ROWS    (BATCH*LSEQ)          // 4096
#define EPSLN   1e-5f
#define NCHK    16
#define CLEN    (LSEQ/NCHK)           // 128
#define KSPL_X  4                      // split-K factor for x_proj

// ================= scratch (static device globals; no allocation) =================
__device__ float g_xz   [(size_t)ROWS * 2 * DINNER];
__device__ float g_u    [(size_t)ROWS * DINNER];
__device__ float g_xdbl [(size_t)ROWS * XDBLW];
__device__ float g_delta[(size_t)ROWS * DINNER];
__device__ float g_xpart[(size_t)KSPL_X * ROWS * XDBLW];
__device__ float g_hloc[(size_t)BATCH*DINNER*NCHK*DSTATE];
__device__ float g_hin [(size_t)BATCH*DINNER*NCHK*DSTATE];
__device__ float g_sumd[(size_t)BATCH*DINNER*NCHK];
__device__ __nv_bfloat16 g_xnh[(size_t)ROWS*DMODEL],  g_xnl[(size_t)ROWS*DMODEL];
__device__ __nv_bfloat16 g_uh [(size_t)ROWS*DINNER],  g_ul [(size_t)ROWS*DINNER];
__device__ __nv_bfloat16 g_xdh[(size_t)ROWS*XDBLW],   g_xdl[(size_t)ROWS*XDBLW];
__device__ __nv_bfloat16 g_ybh[(size_t)ROWS*DINNER],  g_ybl[(size_t)ROWS*DINNER];
__device__ __nv_bfloat16 g_winh[(size_t)2*DINNER*DMODEL], g_winl[(size_t)2*DINNER*DMODEL];
__device__ __nv_bfloat16 g_wxh [(size_t)XDBLW*DINNER],    g_wxl [(size_t)XDBLW*DINNER];
__device__ __nv_bfloat16 g_wdth[(size_t)DINNER*DTRANK],   g_wdtl[(size_t)DINNER*DTRANK];
__device__ __nv_bfloat16 g_wouth[(size_t)DMODEL*DINNER],  g_woutl[(size_t)DMODEL*DINNER];

#define PL_XN 0
#define PL_U 1
#define PL_XD 2
#define PL_YB 3
#define PL_WIN 4
#define PL_WX 5
#define PL_WDT 6
#define PL_WOUT 7
__device__ __forceinline__ void sel_planes(int s, const __nv_bfloat16*& h, const __nv_bfloat16*& l) {
    switch (s) {
        case PL_XN:  h = g_xnh;  l = g_xnl;  break;
        case PL_U:   h = g_uh;   l = g_ul;   break;
        case PL_XD:  h = g_xdh;  l = g_xdl;  break;
        case PL_YB:  h = g_ybh;  l = g_ybl;  break;
        case PL_WIN: h = g_winh; l = g_winl; break;
        case PL_WX:  h = g_wxh;  l = g_wxl;  break;
        case PL_WDT: h = g_wdth; l = g_wdtl; break;
        default:     h = g_wouth;l = g_woutl;break;
    }
}
#define CF_XZ 0
#define CF_XDBL 1
#define CF_DELTA 2
#define CF_XPART 3
#define CF_EXT (-1)

#if defined(__CUDA_ARCH__) && (defined(__CUDA_ARCH_FEAT_SM103_ALL) || defined(__CUDA_ARCH_FEAT_SM100_ALL))
#define HAS_TCGEN05 1
#else
#define HAS_TCGEN05 0
#endif

// ================= helpers =================
__device__ __forceinline__ float softplusf(float x) {
    return (x > 20.f) ? x : log1pf(__expf(x));
}
__device__ __forceinline__ void split1(float v, __nv_bfloat16& h, __nv_bfloat16& l) {
    h = __float2bfloat16(v);
    l = __float2bfloat16(v - __bfloat162float(h));
}

#if HAS_TCGEN05
__device__ __forceinline__ uint32_t smem_u32(const void* p) {
    uint32_t a;
    asm("{ .reg .u64 t; cvta.to.shared.u64 t, %1; cvt.u32.u64 %0, t; }" : "=r"(a) : "l"(p));
    return a;
}
__device__ __forceinline__ uint32_t elect1() {
    uint32_t p;
    asm volatile("{\n\t.reg .pred p;\n\telect.sync _|p, 0xFFFFFFFF;\n\tselp.b32 %0, 1, 0, p;\n\t}" : "=r"(p));
    return p;
}
__device__ __forceinline__ uint64_t mkdesc(uint32_t addr) {
    const uint64_t base = (uint64_t(2) << 61) | (uint64_t(1) << 46)
                        | (uint64_t(64) << 32) | (uint64_t(1) << 16);   // SW128, v1, SBO=64, LBO=1
    return base | ((uint64_t)(addr >> 4) & 0x3FFF);
}
__device__ __forceinline__ void mma_bf16_ss(uint32_t d, uint64_t da, uint64_t db, uint32_t idesc, uint32_t en) {
    asm volatile("{\n\t.reg .pred p;\n\tsetp.ne.u32 p, %5, 0;\n\t"
        "tcgen05.mma.cta_group::1.kind::f16 [%0], %1, %2, %3, {%4, %4, %4, %4}, p;\n\t}"
        :: "r"(d), "l"(da), "l"(db), "r"(idesc), "r"(0u), "r"(en) : "memory");
}
__device__ __forceinline__ void cpasync16(uint32_t dst, const void* src) {
    asm volatile("cp.async.cg.shared.global [%0], [%1], 16;" :: "r"(dst), "l"(src) : "memory");
}
__device__ __forceinline__ void cpasync16z(uint32_t dst, const void* src, bool valid) {
    int sz = valid ? 16 : 0;
    asm volatile("cp.async.cg.shared.global [%0], [%1], 16, %2;" :: "r"(dst), "l"(src), "r"(sz) : "memory");
}
#define CP_COMMIT() asm volatile("cp.async.commit_group;" ::: "memory")
#define CP_WAIT(n)  asm volatile("cp.async.wait_group %0;" :: "n"(n) : "memory")
#define TC_ALLOC(sm, n)   asm volatile("tcgen05.alloc.cta_group::1.sync.aligned.shared::cta.b32 [%0], %1;" :: "r"(sm), "r"(n) : "memory")
#define TC_RELQ()         asm volatile("tcgen05.relinquish_alloc_permit.cta_group::1.sync.aligned;")
#define TC_DEALLOC(t, n)  asm volatile("tcgen05.dealloc.cta_group::1.sync.aligned.b32 %0, %1;" :: "r"(t), "r"(n))
#define TC_COMMIT(mb)     asm volatile("tcgen05.commit.cta_group::1.mbarrier::arrive::one.shared::cluster.b64 [%0];" :: "r"(mb) : "memory")
#define TC_WAIT_LD()      asm volatile("tcgen05.wait::ld.sync.aligned;" ::: "memory")
#define TC_FENCE_AFTER()  asm volatile("tcgen05.fence::after_thread_sync;" ::: "memory")
#define TC_FENCE_BEFORE() asm volatile("tcgen05.fence::before_thread_sync;" ::: "memory")
#define FENCE_ASYNC()     asm volatile("fence.proxy.async.shared::cta;" ::: "memory")
#define MBAR_INIT(mb, c)  asm volatile("mbarrier.init.shared.b64 [%0], %1;" :: "r"(mb), "r"(c) : "memory")
#define MBAR_INVAL(mb)    asm volatile("mbarrier.inval.shared.b64 [%0];" :: "r"(mb) : "memory")
// Bounded wait: never hangs the harness; a protocol bug becomes a rel_err
// diagnostic instead of a dead container. ~2M polls x 10ms hint >> any real wait.
__device__ __forceinline__ void mbar_wait(uint32_t mb, uint32_t ph) {
    uint32_t done;
    asm volatile("{\n\t.reg .pred p;\n\tmbarrier.try_wait.parity.acquire.cta.shared::cta.b64 p, [%1], %2;\n\tselp.b32 %0, 1, 0, p;\n\t}"
        : "=r"(done) : "r"(mb), "r"(ph) : "memory");
    if (done) return;
    for (long i = 0; i < 2000000; i++) {
        asm volatile("{\n\t.reg .pred p;\n\tmbarrier.try_wait.parity.acquire.cta.shared::cta.b64 p, [%1], %2, 0x989680;\n\tselp.b32 %0, 1, 0, p;\n\t}"
            : "=r"(done) : "r"(mb), "r"(ph) : "memory");
        if (done) return;
    }
}
#define LDTM32(r, addr) \
    asm volatile("tcgen05.ld.sync.aligned.32x32b.x32.b32 " \
        "{%0, %1, %2, %3, %4, %5, %6, %7, %8, %9, %10, %11, %12, %13, %14, %15, " \
        " %16, %17, %18, %19, %20, %21, %22, %23, %24, %25, %26, %27, %28, %29, %30, %31}, [%32];" \
        : "=r"((r)[0]),  "=r"((r)[1]),  "=r"((r)[2]),  "=r"((r)[3]), \
          "=r"((r)[4]),  "=r"((r)[5]),  "=r"((r)[6]),  "=r"((r)[7]), \
          "=r"((r)[8]),  "=r"((r)[9]),  "=r"((r)[10]), "=r"((r)[11]), \
          "=r"((r)[12]), "=r"((r)[13]), "=r"((r)[14]), "=r"((r)[15]), \
          "=r"((r)[16]), "=r"((r)[17]), "=r"((r)[18]), "=r"((r)[19]), \
          "=r"((r)[20]), "=r"((r)[21]), "=r"((r)[22]), "=r"((r)[23]), \
          "=r"((r)[24]), "=r"((r)[25]), "=r"((r)[26]), "=r"((r)[27]), \
          "=r"((r)[28]), "=r"((r)[29]), "=r"((r)[30]), "=r"((r)[31]) \
        : "r"(addr))
#define SW128(x) ((x) ^ (((x) >> 3) & 0x70))
#endif  // HAS_TCGEN05

// ================= LayerNorm -> split planes =================
__global__ void ln_kernel(const float* __restrict__ x,
                          const float* __restrict__ w,
                          const float* __restrict__ b)
{
    int row = blockIdx.x;
    int tid = threadIdx.x;
    const float4* xr = (const float4*)(x + (size_t)row * DMODEL);
    float4 v = xr[tid];
    float s  = v.x + v.y + v.z + v.w;
    float sq = v.x*v.x + v.y*v.y + v.z*v.z + v.w*v.w;
    #pragma unroll
    for (int o = 16; o > 0; o >>= 1) {
        s  += __shfl_down_sync(0xffffffffu, s,  o);
        sq += __shfl_down_sync(0xffffffffu, sq, o);
    }
    __shared__ float ss[8], sqs[8];
    int wid = tid >> 5, lid = tid & 31;
    if (lid == 0) { ss[wid] = s; sqs[wid] = sq; }
    __syncthreads();
    __shared__ float s_mu, s_rstd;
    if (tid == 0) {
        float ts = 0.f, tq = 0.f;
        #pragma unroll
        for (int i = 0; i < 8; i++) { ts += ss[i]; tq += sqs[i]; }
        float mu  = ts * (1.f / DMODEL);
        float var = tq * (1.f / DMODEL) - mu * mu;
        s_mu = mu; s_rstd = rsqrtf(var + EPSLN);
    }
    __syncthreads();
    float mu = s_mu, rstd = s_rstd;
    float4 w4 = ((const float4*)w)[tid];
    float4 b4 = ((const float4*)b)[tid];
    float o0 = (v.x - mu) * rstd * w4.x + b4.x;
    float o1 = (v.y - mu) * rstd * w4.y + b4.y;
    float o2 = (v.z - mu) * rstd * w4.z + b4.z;
    float o3 = (v.w - mu) * rstd * w4.w + b4.w;
    __nv_bfloat16 h0,h1,h2,h3,l0,l1,l2,l3;
    split1(o0,h0,l0); split1(o1,h1,l1); split1(o2,h2,l2); split1(o3,h3,l3);
    size_t o = (size_t)row * DMODEL + tid * 4;
    *(__nv_bfloat162*)(g_xnh + o)     = __halves2bfloat162(h0, h1);
    *(__nv_bfloat162*)(g_xnh + o + 2) = __halves2bfloat162(h2, h3);
    *(__nv_bfloat162*)(g_xnl + o)     = __halves2bfloat162(l0, l1);
    *(__nv_bfloat162*)(g_xnl + o + 2) = __halves2bfloat162(l2, l3);
}

// ================= fp32 -> split bf16 weight conversion =================
__global__ void cvt_split(const float* __restrict__ src, int dsel, int n4)
{
    __nv_bfloat16 *dh, *dl;
    switch (dsel) {
        case 0:  dh = g_winh;  dl = g_winl;  break;
        case 1:  dh = g_wxh;   dl = g_wxl;   break;
        case 2:  dh = g_wdth;  dl = g_wdtl;  break;
        default: dh = g_wouth; dl = g_woutl; break;
    }
    int i = blockIdx.x * blockDim.x + threadIdx.x;
    if (i >= n4) return;
    float4 v = ((const float4*)src)[i];
    __nv_bfloat16 h0,h1,h2,h3,l0,l1,l2,l3;
    split1(v.x,h0,l0); split1(v.y,h1,l1); split1(v.z,h2,l2); split1(v.w,h3,l3);
    size_t o = (size_t)i * 4;
    *(__nv_bfloat162*)(dh + o)     = __halves2bfloat162(h0, h1);
    *(__nv_bfloat162*)(dh + o + 2) = __halves2bfloat162(h2, h3);
    *(__nv_bfloat162*)(dl + o)     = __halves2bfloat162(l0, l1);
    *(__nv_bfloat162*)(dl + o + 2) = __halves2bfloat162(l2, l3);
}

// ================= split-bf16 NT GEMM (tcgen05 + cp.async 3-stage pipeline) =====
#define KC       64
#define NSTG     3
#define PLANE_B  16384
#define STAGE_B  (4*PLANE_B)
#define SMD      1024
#define GEMM_SMEM (SMD + NSTG*STAGE_B)   // 197632

#if HAS_TCGEN05
__device__ __forceinline__ void load_stage_async(uint32_t sb, int s, int kb,
    const __nv_bfloat16* __restrict__ Ah, const __nv_bfloat16* __restrict__ Al,
    const __nv_bfloat16* __restrict__ Bh, const __nv_bfloat16* __restrict__ Bl,
    int lda, int ldb, int bm, int bn, int Ntot, int tid)
{
    uint32_t base = sb + SMD + s * STAGE_B;
    #pragma unroll
    for (int i = 0; i < 4; i++) {
        int idx = tid + i * 256;
        int rowi = idx >> 3, u16 = idx & 7;
        uint32_t off = SW128((uint32_t)(rowi * 128 + u16 * 16));
        size_t aoff = (size_t)(bm + rowi) * lda + kb + u16 * 8;
        cpasync16(base + off,           Ah + aoff);
        cpasync16(base + PLANE_B + off, Al + aoff);
        bool ok = (bn + rowi) < Ntot;
        int brow = ok ? (bn + rowi) : (Ntot - 1);
        size_t boff = (size_t)brow * ldb + kb + u16 * 8;
        cpasync16z(base + 2*PLANE_B + off, Bh + boff, ok);
        cpasync16z(base + 3*PLANE_B + off, Bl + boff, ok);
    }
}
#endif

__global__ __launch_bounds__(256)
void tc_gemm(int a_sel, int b_sel, int c_sel, float* __restrict__ Cext,
             int Ntot, int K, int lda, int ldb, int ldc, int ksplits,
             int epi, const float* __restrict__ epi_ptr)
{
    extern __shared__ char smem[];
    const __nv_bfloat16 *Ah, *Al, *Bh, *Bl;
    sel_planes(a_sel, Ah, Al);
    sel_planes(b_sel, Bh, Bl);
    float* C;
    switch (c_sel) {
        case CF_XZ:    C = g_xz;    break;
        case CF_XDBL:  C = g_xdbl;  break;
        case CF_DELTA: C = g_delta; break;
        case CF_XPART: C = g_xpart; break;
        default:       C = Cext;    break;
    }
    int tid = threadIdx.x;
    int ksp = blockIdx.x % ksplits;
    int bn  = (blockIdx.x / ksplits) * 128;
    int bm  = blockIdx.y * 128;
    int Keff = K / ksplits;
    int koff = ksp * Keff;
    size_t cbase = (epi == 4) ? (size_t)ksp * ROWS * XDBLW : 0;

#if HAS_TCGEN05
    uint32_t sb = smem_u32(smem);
    int wid = tid >> 5, lid = tid & 31;
    int NC = Keff / KC;
    int pre = NC < NSTG ? NC : NSTG;

    // prologue loads first (latency overlap with alloc/init)
    for (int i = 0; i < pre; i++) {
        load_stage_async(sb, i, koff + i * KC, Ah, Al, Bh, Bl, lda, ldb, bm, bn, Ntot, tid);
        CP_COMMIT();
    }
    if (wid == 0) { TC_ALLOC(sb + 0, 128); TC_RELQ(); }
    if (tid == 0) {
        MBAR_INIT(sb + 8, 1); MBAR_INIT(sb + 16, 1);
        MBAR_INIT(sb + 24, 1); MBAR_INIT(sb + 32, 1);
    }
    __syncthreads();
    uint32_t tmem;
    asm volatile("ld.shared.b32 %0, [%1];" : "=r"(tmem) : "r"(sb + 0));

    const uint32_t idesc = (1u << 4) | (1u << 7) | (1u << 10)
                         | (16u << 17) | (8u << 24);   // F32 acc, bf16 a/b, N=128, M=128

    for (int c = 0; c < NC; c++) {
        int s = c % NSTG;
        int rem = ((NC < c + NSTG) ? NC : (c + NSTG)) - c - 1;
        if (rem >= 2)      CP_WAIT(2);
        else if (rem == 1) CP_WAIT(1);
        else               CP_WAIT(0);
        FENCE_ASYNC();
        __syncthreads();
        if (wid == 0 && elect1()) {
            uint32_t stg = sb + SMD + s * STAGE_B;
            uint64_t dAh = mkdesc(stg), dAl = mkdesc(stg + PLANE_B);
            uint64_t dBh = mkdesc(stg + 2 * PLANE_B), dBl = mkdesc(stg + 3 * PLANE_B);
            #pragma unroll
            for (int k = 0; k < 4; k++) {
                mma_bf16_ss(tmem, dAh + k*2, dBh + k*2, idesc, (c == 0 && k == 0) ? 0u : 1u);
                mma_bf16_ss(tmem, dAl + k*2, dBh + k*2, idesc, 1u);
                mma_bf16_ss(tmem, dAh + k*2, dBl + k*2, idesc, 1u);
            }
            TC_COMMIT(sb + 8 + 8 * s);
        }
        int nc2 = c + NSTG;
        if (nc2 < NC) {
            mbar_wait(sb + 8 + 8 * s, (c / NSTG) & 1);
            load_stage_async(sb, s, koff + nc2 * KC, Ah, Al, Bh, Bl, lda, ldb, bm, bn, Ntot, tid);
            CP_COMMIT();
        }
    }
    if (wid == 0 && elect1()) TC_COMMIT(sb + 32);
    mbar_wait(sb + 32, 0);
    TC_FENCE_AFTER();

    // epilogue
    {
        int sub = wid & 3;
        int row = bm + sub * 32 + lid;
        int cstart = (wid >> 2) * 64;
        #pragma unroll
        for (int cb = 0; cb < 64; cb += 32) {
            uint32_t dr[32];
            LDTM32(dr, tmem + cstart + cb);
            TC_WAIT_LD();
            #pragma unroll
            for (int j = 0; j < 32; j += 4) {
                int col = bn + cstart + cb + j;
                if (col >= Ntot) continue;
                float4 v = make_float4(__uint_as_float(dr[j]),     __uint_as_float(dr[j + 1]),
                                       __uint_as_float(dr[j + 2]), __uint_as_float(dr[j + 3]));
                if (epi == 1) {
                    float4 r = *(const float4*)(epi_ptr + (size_t)row * ldc + col);
                    v.x += r.x; v.y += r.y; v.z += r.z; v.w += r.w;
                } else if (epi == 2) {
                    v.x = softplusf(v.x + epi_ptr[col]);
                    v.y = softplusf(v.y + epi_ptr[col + 1]);
                    v.z = softplusf(v.z + epi_ptr[col + 2]);
                    v.w = softplusf(v.w + epi_ptr[col + 3]);
                }
                *(float4*)(C + cbase + (size_t)row * ldc + col) = v;
            }
        }
    }
    TC_FENCE_BEFORE();
    __syncthreads();
    if (tid == 0) { MBAR_INVAL(sb + 8); MBAR_INVAL(sb + 16); MBAR_INVAL(sb + 24); MBAR_INVAL(sb + 32); }
    __syncthreads();
    if (wid == 0) TC_DEALLOC(tmem, 128);

#else   // ---------------- FFMA fallback (non-'a' target) ----------------
    float (*As)[128] = (float (*)[128])(smem);
    float (*Bs)[128] = (float (*)[128])(smem + 8192);
    int tx = tid & 15, ty = tid >> 4;

    float acc[8][8];
    #pragma unroll
    for (int i = 0; i < 8; i++)
        #pragma unroll
        for (int j = 0; j < 8; j++) acc[i][j] = 0.f;

    for (int k0 = koff; k0 < koff + Keff; k0 += 16) {
        {
            int row = tid >> 1, ko = (tid & 1) * 8;
            uint4 vh = *(const uint4*)(Ah + (size_t)(bm + row) * lda + k0 + ko);
            uint4 vl = *(const uint4*)(Al + (size_t)(bm + row) * lda + k0 + ko);
            const __nv_bfloat162* ph = (const __nv_bfloat162*)&vh;
            const __nv_bfloat162* pl = (const __nv_bfloat162*)&vl;
            #pragma unroll
            for (int q = 0; q < 4; q++) {
                float2 fh = __bfloat1622float2(ph[q]);
                float2 fl = __bfloat1622float2(pl[q]);
                As[ko + q*2 + 0][row] = fh.x + fl.x;
                As[ko + q*2 + 1][row] = fh.y + fl.y;
            }
        }
        {
            int row = tid >> 1, ko = (tid & 1) * 8;
            uint4 vh = make_uint4(0,0,0,0), vl = make_uint4(0,0,0,0);
            if (bn + row < Ntot) {
                vh = *(const uint4*)(Bh + (size_t)(bn + row) * ldb + k0 + ko);
                vl = *(const uint4*)(Bl + (size_t)(bn + row) * ldb + k0 + ko);
            }
            const __nv_bfloat162* ph = (const __nv_bfloat162*)&vh;
            const __nv_bfloat162* pl = (const __nv_bfloat162*)&vl;
            #pragma unroll
            for (int q = 0; q < 4; q++) {
                float2 fh = __bfloat1622float2(ph[q]);
                float2 fl = __bfloat1622float2(pl[q]);
                Bs[ko + q*2 + 0][row] = fh.x + fl.x;
                Bs[ko + q*2 + 1][row] = fh.y + fl.y;
            }
        }
        __syncthreads();
        #pragma unroll
        for (int k = 0; k < 16; k++) {
            float ra[8], rb[8];
            *(float4*)(ra + 0) = *(const float4*)&As[k][ty * 8 + 0];
            *(float4*)(ra + 4) = *(const float4*)&As[k][ty * 8 + 4];
            *(float4*)(rb + 0) = *(const float4*)&Bs[k][tx * 8 + 0];
            *(float4*)(rb + 4) = *(const float4*)&Bs[k][tx * 8 + 4];
            #pragma unroll
            for (int i = 0; i < 8; i++)
                #pragma unroll
                for (int j = 0; j < 8; j++)
                    acc[i][j] = fmaf(ra[i], rb[j], acc[i][j]);
        }
        __syncthreads();
    }

    #pragma unroll
    for (int i = 0; i < 8; i++) {
        int row = bm + ty * 8 + i;
        #pragma unroll
        for (int j = 0; j < 8; j++) {
            int col = bn + tx * 8 + j;
            if (col < Ntot) {
                float v = acc[i][j];
                if (epi == 1) v += epi_ptr[(size_t)row * ldc + col];
                else if (epi == 2) v = softplusf(v + epi_ptr[col]);
                C[cbase + (size_t)row * ldc + col] = v;
            }
        }
    }
#endif
}

// ================= x_proj split-K reduce -> g_xdbl + planes =================
__global__ void xproj_reduce()
{
    int i = blockIdx.x * blockDim.x + threadIdx.x;
    if (i >= ROWS * XDBLW / 4) return;
    const size_t stride = (size_t)ROWS * XDBLW;
    float4 a = ((const float4*)g_xpart)[i];
    #pragma unroll
    for (int s = 1; s < KSPL_X; s++) {
        float4 p = *(const float4*)(g_xpart + s * stride + (size_t)i * 4);
        a.x += p.x; a.y += p.y; a.z += p.z; a.w += p.w;
    }
    ((float4*)g_xdbl)[i] = a;
    __nv_bfloat16 h0,h1,h2,h3,l0,l1,l2,l3;
    split1(a.x,h0,l0); split1(a.y,h1,l1); split1(a.z,h2,l2); split1(a.w,h3,l3);
    size_t o = (size_t)i * 4;
    *(__nv_bfloat162*)(g_xdh + o)     = __halves2bfloat162(h0, h1);
    *(__nv_bfloat162*)(g_xdh + o + 2) = __halves2bfloat162(h2, h3);
    *(__nv_bfloat162*)(g_xdl + o)     = __halves2bfloat162(l0, l1);
    *(__nv_bfloat162*)(g_xdl + o + 2) = __halves2bfloat162(l2, l3);
}

// ================= causal depthwise conv (w=4) + bias + SiLU -> u + planes ======
__global__ void conv_silu_kernel(const float* __restrict__ cw,
                                 const float* __restrict__ cb)
{
    int idx = blockIdx.x * blockDim.x + threadIdx.x;
    if (idx >= ROWS * DINNER) return;
    int d   = idx & (DINNER - 1);
    int row = idx >> 11;
    int l   = row & (LSEQ - 1);
    float acc = cb[d];
    #pragma unroll
    for (int j = 0; j < 4; j++) {
        int li = l - 3 + j;
        float v = (li >= 0) ? g_xz[(size_t)(row - 3 + j) * (2 * DINNER) + d] : 0.f;
        acc = fmaf(cw[d * 4 + j], v, acc);
    }
    float sig = 1.f / (1.f + __expf(-acc));
    float val = acc * sig;
    g_u[idx] = val;
    __nv_bfloat16 h, lo;
    split1(val, h, lo);
    g_uh[idx] = h;
    g_ul[idx] = lo;
}

// ================= chunked selective scan =================
__device__ __forceinline__ void load_A(const float* __restrict__ A_log, int d,
                                       float (&Av)[DSTATE], float& A0, bool& fast)
{
    #pragma unroll
    for (int s = 0; s < DSTATE; s++) Av[s] = -__expf(A_log[d * DSTATE + s]);
    A0 = Av[0];
    fast = true;
    #pragma unroll
    for (int s = 0; s < DSTATE; s++) {
        float ideal = A0 * (float)(s + 1);
        if (fabsf(Av[s] - ideal) > 1e-4f * fabsf(ideal) + 1e-6f) fast = false;
    }
}

__global__ void scan_pass1(const float* __restrict__ A_log)
{
    int gid = blockIdx.x * blockDim.x + threadIdx.x;
    if (gid >= BATCH * DINNER * NCHK) return;
    int d = gid & (DINNER - 1);
    int b = (gid >> 11) & (BATCH - 1);
    int c = gid >> 12;

    float Av[DSTATE], A0; bool fast;
    load_A(A_log, d, Av, A0, fast);

    float h[DSTATE];
    #pragma unroll
    for (int s = 0; s < DSTATE; s++) h[s] = 0.f;
    float sumd = 0.f;

    size_t row = (size_t)b * LSEQ + (size_t)c * CLEN;
    #pragma unroll 2
    for (int l = 0; l < CLEN; l++, row++) {
        float dlt = g_delta[row * DINNER + d];
        float uu  = g_u[row * DINNER + d];
        const float* xr = g_xdbl + row * XDBLW;
        float Bv[16];
        *(float4*)(Bv + 0)  = *(const float4*)(xr + 64);
        *(float4*)(Bv + 4)  = *(const float4*)(xr + 68);
        *(float4*)(Bv + 8)  = *(const float4*)(xr + 72);
        *(float4*)(Bv + 12) = *(const float4*)(xr + 76);
        sumd += dlt;
        float du = dlt * uu;
        if (fast) {
            float E = __expf(dlt * A0), p = E;
            #pragma unroll
            for (int s = 0; s < DSTATE; s++) { h[s] = fmaf(p, h[s], du * Bv[s]); p *= E; }
        } else {
            #pragma unroll
            for (int s = 0; s < DSTATE; s++) {
                float dA = __expf(dlt * Av[s]);
                h[s] = fmaf(dA, h[s], du * Bv[s]);
            }
        }
    }
    size_t o = (size_t)gid * DSTATE;
    #pragma unroll
    for (int s = 0; s < DSTATE; s += 4)
        *(float4*)(g_hloc + o + s) = make_float4(h[s], h[s+1], h[s+2], h[s+3]);
    g_sumd[gid] = sumd;
}

__global__ void scan_combine(const float* __restrict__ A_log)
{
    int gid = blockIdx.x * blockDim.x + threadIdx.x;
    if (gid >= BATCH * DINNER) return;
    int d = gid & (DINNER - 1);
    int b = gid >> 11;

    float Av[DSTATE], A0; bool fast;
    load_A(A_log, d, Av, A0, fast);

    float hin[DSTATE];
    #pragma unroll
    for (int s = 0; s < DSTATE; s++) hin[s] = 0.f;

    for (int c = 0; c < NCHK; c++) {
        size_t idx = ((size_t)c * BATCH + b) * DINNER + d;
        size_t o = idx * DSTATE;
        #pragma unroll
        for (int s = 0; s < DSTATE; s += 4)
            *(float4*)(g_hin + o + s) = make_float4(hin[s], hin[s+1], hin[s+2], hin[s+3]);
        if (c + 1 < NCHK) {
            float sd = g_sumd[idx];
            float hl[DSTATE];
            #pragma unroll
            for (int s = 0; s < DSTATE; s += 4)
                *(float4*)(hl + s) = *(const float4*)(g_hloc + o + s);
            if (fast) {
                float E = __expf(A0 * sd), p = E;
                #pragma unroll
                for (int s = 0; s < DSTATE; s++) { hin[s] = fmaf(p, hin[s], hl[s]); p *= E; }
            } else {
                #pragma unroll
                for (int s = 0; s < DSTATE; s++)
                    hin[s] = fmaf(__expf(Av[s] * sd), hin[s], hl[s]);
            }
        }
    }
}

__global__ void scan_pass2(const float* __restrict__ A_log,
                           const float* __restrict__ Dp)
{
    int gid = blockIdx.x * blockDim.x + threadIdx.x;
    if (gid >= BATCH * DINNER * NCHK) return;
    int d = gid & (DINNER - 1);
    int b = (gid >> 11) & (BATCH - 1);
    int c = gid >> 12;

    float Av[DSTATE], A0; bool fast;
    load_A(A_log, d, Av, A0, fast);
    float Dd = Dp[d];

    float h[DSTATE];
    size_t o = (size_t)gid * DSTATE;
    #pragma unroll
    for (int s = 0; s < DSTATE; s += 4)
        *(float4*)(h + s) = *(const float4*)(g_hin + o + s);

    size_t row = (size_t)b * LSEQ + (size_t)c * CLEN;
    #pragma unroll 2
    for (int l = 0; l < CLEN; l++, row++) {
        float dlt = g_delta[row * DINNER + d];
        float uu  = g_u[row * DINNER + d];
        float zz  = g_xz[row * (2 * DINNER) + DINNER + d];
        const float* xr = g_xdbl + row * XDBLW;
        float Bv[16], Cv[16];
        *(float4*)(Bv + 0)  = *(const float4*)(xr + 64);
        *(float4*)(Bv + 4)  = *(const float4*)(xr + 68);
        *(float4*)(Bv + 8)  = *(const float4*)(xr + 72);
        *(float4*)(Bv + 12) = *(const float4*)(xr + 76);
        *(float4*)(Cv + 0)  = *(const float4*)(xr + 80);
        *(float4*)(Cv + 4)  = *(const float4*)(xr + 84);
        *(float4*)(Cv + 8)  = *(const float4*)(xr + 88);
        *(float4*)(Cv + 12) = *(const float4*)(xr + 92);
        float du = dlt * uu;
        float y0 = 0.f, y1 = 0.f;
        if (fast) {
            float E = __expf(dlt * A0), p = E;
            #pragma unroll
            for (int s = 0; s < DSTATE; s++) {
                h[s] = fmaf(p, h[s], du * Bv[s]);
                if (s & 1) y1 = fmaf(h[s], Cv[s], y1); else y0 = fmaf(h[s], Cv[s], y0);
                p *= E;
            }
        } else {
            #pragma unroll
            for (int s = 0; s < DSTATE; s++) {
                float dA = __expf(dlt * Av[s]);
                h[s] = fmaf(dA, h[s], du * Bv[s]);
                if (s & 1) y1 = fmaf(h[s], Cv[s], y1); else y0 = fmaf(h[s], Cv[s], y0);
            }
        }
        float y = y0 + y1 + Dd * uu;
        float sig = 1.f / (1.f + __expf(-zz));
        float yv = y * (zz * sig);
        __nv_bfloat16 bh, bl;
        split1(yv, bh, bl);
        size_t oo = row * DINNER + d;
        g_ybh[oo] = bh;
        g_ybl[oo] = bl;
    }
}

// ================= launch =================
extern "C" void kernel_launch(void* const* d_in, const int* in_sizes, int n_in,
                              void* d_out, int out_size)
{
    const float* x      = (const float*)d_in[0];
    const float* norm_w = (const float*)d_in[1];
    const float* norm_b = (const float*)d_in[2];
    const float* W_in   = (const float*)d_in[3];
    const float* conv_w = (const float*)d_in[4];
    const float* conv_b = (const float*)d_in[5];
    const float* W_x    = (const float*)d_in[6];
    const float* W_dt   = (const float*)d_in[7];
    const float* b_dt   = (const float*)d_in[8];
    const float* A_log  = (const float*)d_in[9];
    const float* Dp     = (const float*)d_in[10];
    const float* W_out  = (const float*)d_in[11];
    float* out = (float*)d_out;

    cudaFuncSetAttribute(tc_gemm, cudaFuncAttributeMaxDynamicSharedMemorySize, GEMM_SMEM);

    // 0) weight conversions -> split planes
    {
        int n4;
        n4 = (2*DINNER*DMODEL) / 4; cvt_split<<<(n4 + 255) / 256, 256>>>(W_in, 0, n4);
        n4 = (XDBLW*DINNER) / 4;    cvt_split<<<(n4 + 255) / 256, 256>>>(W_x, 1, n4);
        n4 = (DINNER*DTRANK) / 4;   cvt_split<<<(n4 + 255) / 256, 256>>>(W_dt, 2, n4);
        n4 = (DMODEL*DINNER) / 4;   cvt_split<<<(n4 + 255) / 256, 256>>>(W_out, 3, n4);
    }

    // 1) LayerNorm -> xn planes
    ln_kernel<<<ROWS, 256>>>(x, norm_w, norm_b);

    // 2) in_proj: g_xz = xn @ W_in^T   (N=4096, K=1024)
    tc_gemm<<<dim3(32, 32), 256, GEMM_SMEM>>>(PL_XN, PL_WIN, CF_XZ, nullptr,
        4096, 1024, DMODEL, DMODEL, 2 * DINNER, 1, 0, nullptr);

    // 3) conv + SiLU -> u (fp32 + planes)
    conv_silu_kernel<<<(ROWS * DINNER + 255) / 256, 256>>>(conv_w, conv_b);

    // 4) x_proj: split-K x4 partials, then reduce -> g_xdbl + planes  (N=96, K=2048)
    tc_gemm<<<dim3(KSPL_X, 32), 256, GEMM_SMEM>>>(PL_U, PL_WX, CF_XPART, nullptr,
        96, 2048, DINNER, DINNER, XDBLW, KSPL_X, 4, nullptr);
    xproj_reduce<<<(ROWS * XDBLW / 4 + 255) / 256, 256>>>();

    // 5) dt_proj + softplus: g_delta = softplus(xdbl[:, :64] @ W_dt^T + b_dt)  (N=2048, K=64)
    tc_gemm<<<dim3(16, 32), 256, GEMM_SMEM>>>(PL_XD, PL_WDT, CF_DELTA, nullptr,
        2048, 64, XDBLW, DTRANK, DINNER, 1, 2, b_dt);

    // 6) chunked scan: pass1 -> combine -> pass2
    scan_pass1<<<(BATCH * DINNER * NCHK + 255) / 256, 256>>>(A_log);
    scan_combine<<<(BATCH * DINNER + 255) / 256, 256>>>(A_log);
    scan_pass2<<<(BATCH * DINNER * NCHK + 255) / 256, 256>>>(A_log, Dp);

    // 7) out_proj + residual: out = ybar @ W_out^T + x  (N=1024, K=2048)
    tc_gemm<<<dim3(8, 32), 256, GEMM_SMEM>>>(PL_YB, PL_WOUT, CF_EXT, out,
        1024, 2048, DINNER, DINNER, DMODEL, 1, 1, x);
}

// round 17
// speedup vs baseline: 5.9785x; 1.0333x over previous
#include <cuda_runtime.h>
#include <cuda_bf16.h>
#include <stdint.h>
#include <math.h>

#define BATCH   2
#define LSEQ    2048
#define DMODEL  1024
#define DINNER  2048
#define DSTATE  16
#define DTRANK  64
#define XDBLW   (DTRANK + 2*DSTATE)   // 96
#define ROWS    (BATCH*LSEQ)          // 4096
#define EPSLN   1e-5f
#define NCHK    16
#define CLEN    (LSEQ/NCHK)           // 128
#define KSPL_X  4

// ================= scratch (static device globals; no allocation) =================
__device__ float g_xz   [(size_t)ROWS * 2 * DINNER];
__device__ float g_u    [(size_t)ROWS * DINNER];
__device__ float g_xdbl [(size_t)ROWS * XDBLW];
__device__ float g_delta[(size_t)ROWS * DINNER];
__device__ float g_xpart[(size_t)KSPL_X * ROWS * XDBLW];
__device__ float g_hloc[(size_t)BATCH*DINNER*NCHK*DSTATE];
__device__ float g_hin [(size_t)BATCH*DINNER*NCHK*DSTATE];
__device__ float g_sumd[(size_t)BATCH*DINNER*NCHK];
__device__ __nv_bfloat16 g_xnh[(size_t)ROWS*DMODEL],  g_xnl[(size_t)ROWS*DMODEL];
__device__ __nv_bfloat16 g_uh [(size_t)ROWS*DINNER],  g_ul [(size_t)ROWS*DINNER];
__device__ __nv_bfloat16 g_xdh[(size_t)ROWS*XDBLW],   g_xdl[(size_t)ROWS*XDBLW];
__device__ __nv_bfloat16 g_ybh[(size_t)ROWS*DINNER],  g_ybl[(size_t)ROWS*DINNER];
__device__ __nv_bfloat16 g_winh[(size_t)2*DINNER*DMODEL], g_winl[(size_t)2*DINNER*DMODEL];
__device__ __nv_bfloat16 g_wxh [(size_t)XDBLW*DINNER],    g_wxl [(size_t)XDBLW*DINNER];
__device__ __nv_bfloat16 g_wdth[(size_t)DINNER*DTRANK],   g_wdtl[(size_t)DINNER*DTRANK];
__device__ __nv_bfloat16 g_wouth[(size_t)DMODEL*DINNER],  g_woutl[(size_t)DMODEL*DINNER];

#define PL_XN 0
#define PL_U 1
#define PL_XD 2
#define PL_YB 3
#define PL_WIN 4
#define PL_WX 5
#define PL_WDT 6
#define PL_WOUT 7
__device__ __forceinline__ void sel_planes(int s, const __nv_bfloat16*& h, const __nv_bfloat16*& l) {
    switch (s) {
        case PL_XN:  h = g_xnh;  l = g_xnl;  break;
        case PL_U:   h = g_uh;   l = g_ul;   break;
        case PL_XD:  h = g_xdh;  l = g_xdl;  break;
        case PL_YB:  h = g_ybh;  l = g_ybl;  break;
        case PL_WIN: h = g_winh; l = g_winl; break;
        case PL_WX:  h = g_wxh;  l = g_wxl;  break;
        case PL_WDT: h = g_wdth; l = g_wdtl; break;
        default:     h = g_wouth;l = g_woutl;break;
    }
}
#define CF_XZ 0
#define CF_XDBL 1
#define CF_DELTA 2
#define CF_XPART 3
#define CF_EXT (-1)

#if defined(__CUDA_ARCH__) && (defined(__CUDA_ARCH_FEAT_SM103_ALL) || defined(__CUDA_ARCH_FEAT_SM100_ALL))
#define HAS_TCGEN05 1
#else
#define HAS_TCGEN05 0
#endif

// ================= helpers =================
__device__ __forceinline__ float softplusf(float x) {
    return (x > 20.f) ? x : log1pf(__expf(x));
}
__device__ __forceinline__ void split1(float v, __nv_bfloat16& h, __nv_bfloat16& l) {
    h = __float2bfloat16(v);
    l = __float2bfloat16(v - __bfloat162float(h));
}

#if HAS_TCGEN05
__device__ __forceinline__ uint32_t smem_u32(const void* p) {
    uint32_t a;
    asm("{ .reg .u64 t; cvta.to.shared.u64 t, %1; cvt.u32.u64 %0, t; }" : "=r"(a) : "l"(p));
    return a;
}
__device__ __forceinline__ uint32_t elect1() {
    uint32_t p;
    asm volatile("{\n\t.reg .pred p;\n\telect.sync _|p, 0xFFFFFFFF;\n\tselp.b32 %0, 1, 0, p;\n\t}" : "=r"(p));
    return p;
}
__device__ __forceinline__ uint64_t mkdesc(uint32_t addr) {
    const uint64_t base = (uint64_t(2) << 61) | (uint64_t(1) << 46)
                        | (uint64_t(64) << 32) | (uint64_t(1) << 16);   // SW128, v1, SBO=64, LBO=1
    return base | ((uint64_t)(addr >> 4) & 0x3FFF);
}
__device__ __forceinline__ void mma_bf16_ss(uint32_t d, uint64_t da, uint64_t db, uint32_t idesc, uint32_t en) {
    asm volatile("{\n\t.reg .pred p;\n\tsetp.ne.u32 p, %5, 0;\n\t"
        "tcgen05.mma.cta_group::1.kind::f16 [%0], %1, %2, %3, {%4, %4, %4, %4}, p;\n\t}"
        :: "r"(d), "l"(da), "l"(db), "r"(idesc), "r"(0u), "r"(en) : "memory");
}
__device__ __forceinline__ void cpasync16(uint32_t dst, const void* src) {
    asm volatile("cp.async.cg.shared.global [%0], [%1], 16;" :: "r"(dst), "l"(src) : "memory");
}
__device__ __forceinline__ void cpasync16z(uint32_t dst, const void* src, bool valid) {
    int sz = valid ? 16 : 0;
    asm volatile("cp.async.cg.shared.global [%0], [%1], 16, %2;" :: "r"(dst), "l"(src), "r"(sz) : "memory");
}
#define CP_COMMIT() asm volatile("cp.async.commit_group;" ::: "memory")
#define CP_WAIT(n)  asm volatile("cp.async.wait_group %0;" :: "n"(n) : "memory")
#define TC_ALLOC(sm, n)   asm volatile("tcgen05.alloc.cta_group::1.sync.aligned.shared::cta.b32 [%0], %1;" :: "r"(sm), "r"(n) : "memory")
#define TC_RELQ()         asm volatile("tcgen05.relinquish_alloc_permit.cta_group::1.sync.aligned;")
#define TC_DEALLOC(t, n)  asm volatile("tcgen05.dealloc.cta_group::1.sync.aligned.b32 %0, %1;" :: "r"(t), "r"(n))
#define TC_COMMIT(mb)     asm volatile("tcgen05.commit.cta_group::1.mbarrier::arrive::one.shared::cluster.b64 [%0];" :: "r"(mb) : "memory")
#define TC_WAIT_LD()      asm volatile("tcgen05.wait::ld.sync.aligned;" ::: "memory")
#define TC_FENCE_AFTER()  asm volatile("tcgen05.fence::after_thread_sync;" ::: "memory")
#define TC_FENCE_BEFORE() asm volatile("tcgen05.fence::before_thread_sync;" ::: "memory")
#define FENCE_ASYNC()     asm volatile("fence.proxy.async.shared::cta;" ::: "memory")
#define MBAR_INIT(mb, c)  asm volatile("mbarrier.init.shared.b64 [%0], %1;" :: "r"(mb), "r"(c) : "memory")
#define MBAR_INVAL(mb)    asm volatile("mbarrier.inval.shared.b64 [%0];" :: "r"(mb) : "memory")
// Bounded wait: never hangs the harness; a protocol bug becomes rel_err, not a dead container.
__device__ __forceinline__ void mbar_wait(uint32_t mb, uint32_t ph) {
    uint32_t done;
    asm volatile("{\n\t.reg .pred p;\n\tmbarrier.try_wait.parity.acquire.cta.shared::cta.b64 p, [%1], %2;\n\tselp.b32 %0, 1, 0, p;\n\t}"
        : "=r"(done) : "r"(mb), "r"(ph) : "memory");
    if (done) return;
    for (long i = 0; i < 2000000; i++) {
        asm volatile("{\n\t.reg .pred p;\n\tmbarrier.try_wait.parity.acquire.cta.shared::cta.b64 p, [%1], %2, 0x989680;\n\tselp.b32 %0, 1, 0, p;\n\t}"
            : "=r"(done) : "r"(mb), "r"(ph) : "memory");
        if (done) return;
    }
}
#define LDTM32(r, addr) \
    asm volatile("tcgen05.ld.sync.aligned.32x32b.x32.b32 " \
        "{%0, %1, %2, %3, %4, %5, %6, %7, %8, %9, %10, %11, %12, %13, %14, %15, " \
        " %16, %17, %18, %19, %20, %21, %22, %23, %24, %25, %26, %27, %28, %29, %30, %31}, [%32];" \
        : "=r"((r)[0]),  "=r"((r)[1]),  "=r"((r)[2]),  "=r"((r)[3]), \
          "=r"((r)[4]),  "=r"((r)[5]),  "=r"((r)[6]),  "=r"((r)[7]), \
          "=r"((r)[8]),  "=r"((r)[9]),  "=r"((r)[10]), "=r"((r)[11]), \
          "=r"((r)[12]), "=r"((r)[13]), "=r"((r)[14]), "=r"((r)[15]), \
          "=r"((r)[16]), "=r"((r)[17]), "=r"((r)[18]), "=r"((r)[19]), \
          "=r"((r)[20]), "=r"((r)[21]), "=r"((r)[22]), "=r"((r)[23]), \
          "=r"((r)[24]), "=r"((r)[25]), "=r"((r)[26]), "=r"((r)[27]), \
          "=r"((r)[28]), "=r"((r)[29]), "=r"((r)[30]), "=r"((r)[31]) \
        : "r"(addr))
#define SW128(x) ((x) ^ (((x) >> 3) & 0x70))
#endif  // HAS_TCGEN05

// ================= LayerNorm -> split planes =================
__global__ void ln_kernel(const float* __restrict__ x,
                          const float* __restrict__ w,
                          const float* __restrict__ b)
{
    int row = blockIdx.x;
    int tid = threadIdx.x;
    const float4* xr = (const float4*)(x + (size_t)row * DMODEL);
    float4 v = xr[tid];
    float s  = v.x + v.y + v.z + v.w;
    float sq = v.x*v.x + v.y*v.y + v.z*v.z + v.w*v.w;
    #pragma unroll
    for (int o = 16; o > 0; o >>= 1) {
        s  += __shfl_down_sync(0xffffffffu, s,  o);
        sq += __shfl_down_sync(0xffffffffu, sq, o);
    }
    __shared__ float ss[8], sqs[8];
    int wid = tid >> 5, lid = tid & 31;
    if (lid == 0) { ss[wid] = s; sqs[wid] = sq; }
    __syncthreads();
    __shared__ float s_mu, s_rstd;
    if (tid == 0) {
        float ts = 0.f, tq = 0.f;
        #pragma unroll
        for (int i = 0; i < 8; i++) { ts += ss[i]; tq += sqs[i]; }
        float mu  = ts * (1.f / DMODEL);
        float var = tq * (1.f / DMODEL) - mu * mu;
        s_mu = mu; s_rstd = rsqrtf(var + EPSLN);
    }
    __syncthreads();
    float mu = s_mu, rstd = s_rstd;
    float4 w4 = ((const float4*)w)[tid];
    float4 b4 = ((const float4*)b)[tid];
    float o0 = (v.x - mu) * rstd * w4.x + b4.x;
    float o1 = (v.y - mu) * rstd * w4.y + b4.y;
    float o2 = (v.z - mu) * rstd * w4.z + b4.z;
    float o3 = (v.w - mu) * rstd * w4.w + b4.w;
    __nv_bfloat16 h0,h1,h2,h3,l0,l1,l2,l3;
    split1(o0,h0,l0); split1(o1,h1,l1); split1(o2,h2,l2); split1(o3,h3,l3);
    size_t o = (size_t)row * DMODEL + tid * 4;
    *(__nv_bfloat162*)(g_xnh + o)     = __halves2bfloat162(h0, h1);
    *(__nv_bfloat162*)(g_xnh + o + 2) = __halves2bfloat162(h2, h3);
    *(__nv_bfloat162*)(g_xnl + o)     = __halves2bfloat162(l0, l1);
    *(__nv_bfloat162*)(g_xnl + o + 2) = __halves2bfloat162(l2, l3);
}

// ================= fused weight conversion (all 4 weights, one launch) ==========
#define CVT_N0 (2*DINNER*DMODEL/4)
#define CVT_N1 (CVT_N0 + XDBLW*DINNER/4)
#define CVT_N2 (CVT_N1 + DINNER*DTRANK/4)
#define CVT_N3 (CVT_N2 + DMODEL*DINNER/4)
__global__ void cvt_all(const float* __restrict__ Win, const float* __restrict__ Wx,
                        const float* __restrict__ Wdt, const float* __restrict__ Wout)
{
    int i = blockIdx.x * blockDim.x + threadIdx.x;
    if (i >= CVT_N3) return;
    const float* src; __nv_bfloat16 *dh, *dl; int off;
    if (i < CVT_N0)      { src = Win;  dh = g_winh;  dl = g_winl;  off = i; }
    else if (i < CVT_N1) { src = Wx;   dh = g_wxh;   dl = g_wxl;   off = i - CVT_N0; }
    else if (i < CVT_N2) { src = Wdt;  dh = g_wdth;  dl = g_wdtl;  off = i - CVT_N1; }
    else                 { src = Wout; dh = g_wouth; dl = g_woutl; off = i - CVT_N2; }
    float4 v = ((const float4*)src)[off];
    __nv_bfloat16 h0,h1,h2,h3,l0,l1,l2,l3;
    split1(v.x,h0,l0); split1(v.y,h1,l1); split1(v.z,h2,l2); split1(v.w,h3,l3);
    size_t o = (size_t)off * 4;
    *(__nv_bfloat162*)(dh + o)     = __halves2bfloat162(h0, h1);
    *(__nv_bfloat162*)(dh + o + 2) = __halves2bfloat162(h2, h3);
    *(__nv_bfloat162*)(dl + o)     = __halves2bfloat162(l0, l1);
    *(__nv_bfloat162*)(dl + o + 2) = __halves2bfloat162(l2, l3);
}

// ================= split-bf16 NT GEMM, templated tile width =====================
#define KC       64
#define PLANE_A  16384
#define SMD      1024
#define GEMM_SMEM 197632

#if HAS_TCGEN05
template<int BN>
__device__ __forceinline__ void load_stage_async(uint32_t sb, int stage_b, int s, int kb,
    const __nv_bfloat16* __restrict__ Ah, const __nv_bfloat16* __restrict__ Al,
    const __nv_bfloat16* __restrict__ Bh, const __nv_bfloat16* __restrict__ Bl,
    int lda, int ldb, int bm, int bn, int Ntot, int tid)
{
    const int PLANE_BB = BN * 128;
    uint32_t base = sb + SMD + s * stage_b;
    #pragma unroll
    for (int i = 0; i < 4; i++) {
        int idx = tid + i * 256;
        int rowi = idx >> 3, u16 = idx & 7;
        uint32_t off = SW128((uint32_t)(rowi * 128 + u16 * 16));
        size_t aoff = (size_t)(bm + rowi) * lda + kb + u16 * 8;
        cpasync16(base + off,           Ah + aoff);
        cpasync16(base + PLANE_A + off, Al + aoff);
    }
    #pragma unroll
    for (int i = 0; i < BN / 32; i++) {
        int idx = tid + i * 256;
        int rowi = idx >> 3, u16 = idx & 7;
        uint32_t off = SW128((uint32_t)(rowi * 128 + u16 * 16));
        bool ok = (bn + rowi) < Ntot;
        int brow = ok ? (bn + rowi) : (Ntot - 1);
        size_t boff = (size_t)brow * ldb + kb + u16 * 8;
        cpasync16z(base + 2*PLANE_A + off,            Bh + boff, ok);
        cpasync16z(base + 2*PLANE_A + PLANE_BB + off, Bl + boff, ok);
    }
}
#endif

template<int BN, int NSTG>
__global__ __launch_bounds__(256)
void tc_gemm(int a_sel, int b_sel, int c_sel, float* __restrict__ Cext,
             int Ntot, int K, int lda, int ldb, int ldc, int ksplits,
             int epi, const float* __restrict__ epi_ptr)
{
    extern __shared__ char smem[];
    const __nv_bfloat16 *Ah, *Al, *Bh, *Bl;
    sel_planes(a_sel, Ah, Al);
    sel_planes(b_sel, Bh, Bl);
    float* C;
    switch (c_sel) {
        case CF_XZ:    C = g_xz;    break;
        case CF_XDBL:  C = g_xdbl;  break;
        case CF_DELTA: C = g_delta; break;
        case CF_XPART: C = g_xpart; break;
        default:       C = Cext;    break;
    }
    int tid = threadIdx.x;
    int ksp = blockIdx.x % ksplits;
    int bn  = (blockIdx.x / ksplits) * BN;
    int bm  = blockIdx.y * 128;
    int Keff = K / ksplits;
    int koff = ksp * Keff;
    size_t cbase = (epi == 4) ? (size_t)ksp * ROWS * XDBLW : 0;

#if HAS_TCGEN05
    const int PLANE_BB = BN * 128;
    const int STAGE_B  = 2 * PLANE_A + 2 * PLANE_BB;
    uint32_t sb = smem_u32(smem);
    int wid = tid >> 5, lid = tid & 31;
    int NC = Keff / KC;
    int pre = NC < NSTG ? NC : NSTG;

    for (int i = 0; i < pre; i++) {
        load_stage_async<BN>(sb, STAGE_B, i, koff + i * KC, Ah, Al, Bh, Bl, lda, ldb, bm, bn, Ntot, tid);
        CP_COMMIT();
    }
    if (wid == 0) { TC_ALLOC(sb + 0, BN); TC_RELQ(); }
    if (tid == 0) {
        #pragma unroll
        for (int s = 0; s <= NSTG; s++) MBAR_INIT(sb + 8 + 8 * s, 1);
    }
    __syncthreads();
    uint32_t tmem;
    asm volatile("ld.shared.b32 %0, [%1];" : "=r"(tmem) : "r"(sb + 0));

    const uint32_t idesc = (1u << 4) | (1u << 7) | (1u << 10)
                         | ((uint32_t)(BN / 8) << 17) | (8u << 24);   // F32 acc, bf16, N=BN, M=128

    for (int c = 0; c < NC; c++) {
        int s = c % NSTG;
        int rem = ((NC < c + NSTG) ? NC : (c + NSTG)) - c - 1;
        if (rem >= 2)      CP_WAIT(2);
        else if (rem == 1) CP_WAIT(1);
        else               CP_WAIT(0);
        FENCE_ASYNC();
        __syncthreads();
        if (wid == 0 && elect1()) {
            uint32_t stg = sb + SMD + s * STAGE_B;
            uint64_t dAh = mkdesc(stg), dAl = mkdesc(stg + PLANE_A);
            uint64_t dBh = mkdesc(stg + 2 * PLANE_A), dBl = mkdesc(stg + 2 * PLANE_A + PLANE_BB);
            #pragma unroll
            for (int k = 0; k < 4; k++) {
                mma_bf16_ss(tmem, dAh + k*2, dBh + k*2, idesc, (c == 0 && k == 0) ? 0u : 1u);
                mma_bf16_ss(tmem, dAl + k*2, dBh + k*2, idesc, 1u);
                mma_bf16_ss(tmem, dAh + k*2, dBl + k*2, idesc, 1u);
            }
            TC_COMMIT(sb + 8 + 8 * s);
        }
        int nc2 = c + NSTG;
        if (nc2 < NC) {
            mbar_wait(sb + 8 + 8 * s, (c / NSTG) & 1);
            load_stage_async<BN>(sb, STAGE_B, s, koff + nc2 * KC, Ah, Al, Bh, Bl, lda, ldb, bm, bn, Ntot, tid);
            CP_COMMIT();
        }
    }
    if (wid == 0 && elect1()) TC_COMMIT(sb + 8 + 8 * NSTG);
    mbar_wait(sb + 8 + 8 * NSTG, 0);
    TC_FENCE_AFTER();

    // epilogue
    {
        int sub = wid & 3;
        int row = bm + sub * 32 + lid;
        int cstart = (wid >> 2) * (BN / 2);
        #pragma unroll
        for (int cb = 0; cb < BN / 2; cb += 32) {
            uint32_t dr[32];
            LDTM32(dr, tmem + cstart + cb);
            TC_WAIT_LD();
            #pragma unroll
            for (int j = 0; j < 32; j += 4) {
                int col = bn + cstart + cb + j;
                if (col >= Ntot) continue;
                float4 v = make_float4(__uint_as_float(dr[j]),     __uint_as_float(dr[j + 1]),
                                       __uint_as_float(dr[j + 2]), __uint_as_float(dr[j + 3]));
                if (epi == 1) {
                    float4 r = *(const float4*)(epi_ptr + (size_t)row * ldc + col);
                    v.x += r.x; v.y += r.y; v.z += r.z; v.w += r.w;
                } else if (epi == 2) {
                    v.x = softplusf(v.x + epi_ptr[col]);
                    v.y = softplusf(v.y + epi_ptr[col + 1]);
                    v.z = softplusf(v.z + epi_ptr[col + 2]);
                    v.w = softplusf(v.w + epi_ptr[col + 3]);
                }
                *(float4*)(C + cbase + (size_t)row * ldc + col) = v;
            }
        }
    }
    TC_FENCE_BEFORE();
    __syncthreads();
    if (tid == 0) {
        #pragma unroll
        for (int s = 0; s <= NSTG; s++) MBAR_INVAL(sb + 8 + 8 * s);
    }
    __syncthreads();
    if (wid == 0) TC_DEALLOC(tmem, BN);

#else   // ---------------- FFMA fallback (non-'a' target; correctness only) -------
    float (*As)[128] = (float (*)[128])(smem);
    float (*Bs)[128] = (float (*)[128])(smem + 8192);
    int tx = tid & 15, ty = tid >> 4;

    for (int bns = 0; bns < BN; bns += 128) {
        int bn2 = bn + bns;
        float acc[8][8];
        #pragma unroll
        for (int i = 0; i < 8; i++)
            #pragma unroll
            for (int j = 0; j < 8; j++) acc[i][j] = 0.f;

        for (int k0 = koff; k0 < koff + Keff; k0 += 16) {
            {
                int row = tid >> 1, ko = (tid & 1) * 8;
                uint4 vh = *(const uint4*)(Ah + (size_t)(bm + row) * lda + k0 + ko);
                uint4 vl = *(const uint4*)(Al + (size_t)(bm + row) * lda + k0 + ko);
                const __nv_bfloat162* ph = (const __nv_bfloat162*)&vh;
                const __nv_bfloat162* pl = (const __nv_bfloat162*)&vl;
                #pragma unroll
                for (int q = 0; q < 4; q++) {
                    float2 fh = __bfloat1622float2(ph[q]);
                    float2 fl = __bfloat1622float2(pl[q]);
                    As[ko + q*2 + 0][row] = fh.x + fl.x;
                    As[ko + q*2 + 1][row] = fh.y + fl.y;
                }
            }
            {
                int row = tid >> 1, ko = (tid & 1) * 8;
                uint4 vh = make_uint4(0,0,0,0), vl = make_uint4(0,0,0,0);
                if (bn2 + row < Ntot) {
                    vh = *(const uint4*)(Bh + (size_t)(bn2 + row) * ldb + k0 + ko);
                    vl = *(const uint4*)(Bl + (size_t)(bn2 + row) * ldb + k0 + ko);
                }
                const __nv_bfloat162* ph = (const __nv_bfloat162*)&vh;
                const __nv_bfloat162* pl = (const __nv_bfloat162*)&vl;
                #pragma unroll
                for (int q = 0; q < 4; q++) {
                    float2 fh = __bfloat1622float2(ph[q]);
                    float2 fl = __bfloat1622float2(pl[q]);
                    Bs[ko + q*2 + 0][row] = fh.x + fl.x;
                    Bs[ko + q*2 + 1][row] = fh.y + fl.y;
                }
            }
            __syncthreads();
            #pragma unroll
            for (int k = 0; k < 16; k++) {
                float ra[8], rb[8];
                *(float4*)(ra + 0) = *(const float4*)&As[k][ty * 8 + 0];
                *(float4*)(ra + 4) = *(const float4*)&As[k][ty * 8 + 4];
                *(float4*)(rb + 0) = *(const float4*)&Bs[k][tx * 8 + 0];
                *(float4*)(rb + 4) = *(const float4*)&Bs[k][tx * 8 + 4];
                #pragma unroll
                for (int i = 0; i < 8; i++)
                    #pragma unroll
                    for (int j = 0; j < 8; j++)
                        acc[i][j] = fmaf(ra[i], rb[j], acc[i][j]);
            }
            __syncthreads();
        }

        #pragma unroll
        for (int i = 0; i < 8; i++) {
            int row = bm + ty * 8 + i;
            #pragma unroll
            for (int j = 0; j < 8; j++) {
                int col = bn2 + tx * 8 + j;
                if (col < Ntot) {
                    float v = acc[i][j];
                    if (epi == 1) v += epi_ptr[(size_t)row * ldc + col];
                    else if (epi == 2) v = softplusf(v + epi_ptr[col]);
                    C[cbase + (size_t)row * ldc + col] = v;
                }
            }
        }
        __syncthreads();
    }
#endif
}

// ================= x_proj split-K reduce -> g_xdbl + planes =================
__global__ void xproj_reduce()
{
    int i = blockIdx.x * blockDim.x + threadIdx.x;
    if (i >= ROWS * XDBLW / 4) return;
    const size_t stride = (size_t)ROWS * XDBLW;
    float4 a = ((const float4*)g_xpart)[i];
    #pragma unroll
    for (int s = 1; s < KSPL_X; s++) {
        float4 p = *(const float4*)(g_xpart + s * stride + (size_t)i * 4);
        a.x += p.x; a.y += p.y; a.z += p.z; a.w += p.w;
    }
    ((float4*)g_xdbl)[i] = a;
    __nv_bfloat16 h0,h1,h2,h3,l0,l1,l2,l3;
    split1(a.x,h0,l0); split1(a.y,h1,l1); split1(a.z,h2,l2); split1(a.w,h3,l3);
    size_t o = (size_t)i * 4;
    *(__nv_bfloat162*)(g_xdh + o)     = __halves2bfloat162(h0, h1);
    *(__nv_bfloat162*)(g_xdh + o + 2) = __halves2bfloat162(h2, h3);
    *(__nv_bfloat162*)(g_xdl + o)     = __halves2bfloat162(l0, l1);
    *(__nv_bfloat162*)(g_xdl + o + 2) = __halves2bfloat162(l2, l3);
}

// ================= causal depthwise conv (w=4) + bias + SiLU, x4 vectorized =====
__global__ void conv_silu_kernel(const float* __restrict__ cw,
                                 const float* __restrict__ cb)
{
    int idx4 = blockIdx.x * blockDim.x + threadIdx.x;
    if (idx4 >= ROWS * DINNER / 4) return;
    int d4  = (idx4 & (DINNER / 4 - 1)) * 4;
    int row = idx4 >> 9;
    int l   = row & (LSEQ - 1);

    float4 cw0 = *(const float4*)(cw + (d4 + 0) * 4);
    float4 cw1 = *(const float4*)(cw + (d4 + 1) * 4);
    float4 cw2 = *(const float4*)(cw + (d4 + 2) * 4);
    float4 cw3 = *(const float4*)(cw + (d4 + 3) * 4);
    float4 acc = *(const float4*)(cb + d4);

    const float* cwp0 = (const float*)&cw0;
    const float* cwp1 = (const float*)&cw1;
    const float* cwp2 = (const float*)&cw2;
    const float* cwp3 = (const float*)&cw3;
    #pragma unroll
    for (int j = 0; j < 4; j++) {
        int li = l - 3 + j;
        if (li < 0) continue;
        float4 v = *(const float4*)(g_xz + (size_t)(row - 3 + j) * (2 * DINNER) + d4);
        acc.x = fmaf(cwp0[j], v.x, acc.x);
        acc.y = fmaf(cwp1[j], v.y, acc.y);
        acc.z = fmaf(cwp2[j], v.z, acc.z);
        acc.w = fmaf(cwp3[j], v.w, acc.w);
    }
    float4 val;
    val.x = acc.x / (1.f + __expf(-acc.x));
    val.y = acc.y / (1.f + __expf(-acc.y));
    val.z = acc.z / (1.f + __expf(-acc.z));
    val.w = acc.w / (1.f + __expf(-acc.w));
    size_t o = (size_t)row * DINNER + d4;
    *(float4*)(g_u + o) = val;
    __nv_bfloat16 h0,h1,h2,h3,l0,l1,l2,l3;
    split1(val.x,h0,l0); split1(val.y,h1,l1); split1(val.z,h2,l2); split1(val.w,h3,l3);
    *(__nv_bfloat162*)(g_uh + o)     = __halves2bfloat162(h0, h1);
    *(__nv_bfloat162*)(g_uh + o + 2) = __halves2bfloat162(h2, h3);
    *(__nv_bfloat162*)(g_ul + o)     = __halves2bfloat162(l0, l1);
    *(__nv_bfloat162*)(g_ul + o + 2) = __halves2bfloat162(l2, l3);
}

// ================= chunked selective scan =================
__device__ __forceinline__ void load_A(const float* __restrict__ A_log, int d,
                                       float (&Av)[DSTATE], float& A0, bool& fast)
{
    #pragma unroll
    for (int s = 0; s < DSTATE; s++) Av[s] = -__expf(A_log[d * DSTATE + s]);
    A0 = Av[0];
    fast = true;
    #pragma unroll
    for (int s = 0; s < DSTATE; s++) {
        float ideal = A0 * (float)(s + 1);
        if (fabsf(Av[s] - ideal) > 1e-4f * fabsf(ideal) + 1e-6f) fast = false;
    }
}

__global__ void scan_pass1(const float* __restrict__ A_log)
{
    int gid = blockIdx.x * blockDim.x + threadIdx.x;
    if (gid >= BATCH * DINNER * NCHK) return;
    int d = gid & (DINNER - 1);
    int b = (gid >> 11) & (BATCH - 1);
    int c = gid >> 12;

    float Av[DSTATE], A0; bool fast;
    load_A(A_log, d, Av, A0, fast);

    float h[DSTATE];
    #pragma unroll
    for (int s = 0; s < DSTATE; s++) h[s] = 0.f;
    float sumd = 0.f;

    size_t row = (size_t)b * LSEQ + (size_t)c * CLEN;
    #pragma unroll 2
    for (int l = 0; l < CLEN; l++, row++) {
        float dlt = g_delta[row * DINNER + d];
        float uu  = g_u[row * DINNER + d];
        const float* xr = g_xdbl + row * XDBLW;
        float Bv[16];
        *(float4*)(Bv + 0)  = *(const float4*)(xr + 64);
        *(float4*)(Bv + 4)  = *(const float4*)(xr + 68);
        *(float4*)(Bv + 8)  = *(const float4*)(xr + 72);
        *(float4*)(Bv + 12) = *(const float4*)(xr + 76);
        sumd += dlt;
        float du = dlt * uu;
        if (fast) {
            float E = __expf(dlt * A0), p = E;
            #pragma unroll
            for (int s = 0; s < DSTATE; s++) { h[s] = fmaf(p, h[s], du * Bv[s]); p *= E; }
        } else {
            #pragma unroll
            for (int s = 0; s < DSTATE; s++) {
                float dA = __expf(dlt * Av[s]);
                h[s] = fmaf(dA, h[s], du * Bv[s]);
            }
        }
    }
    size_t o = (size_t)gid * DSTATE;
    #pragma unroll
    for (int s = 0; s < DSTATE; s += 4)
        *(float4*)(g_hloc + o + s) = make_float4(h[s], h[s+1], h[s+2], h[s+3]);
    g_sumd[gid] = sumd;
}

__global__ void scan_combine(const float* __restrict__ A_log)
{
    int gid = blockIdx.x * blockDim.x + threadIdx.x;
    if (gid >= BATCH * DINNER) return;
    int d = gid & (DINNER - 1);
    int b = gid >> 11;

    float Av[DSTATE], A0; bool fast;
    load_A(A_log, d, Av, A0, fast);

    float hin[DSTATE];
    #pragma unroll
    for (int s = 0; s < DSTATE; s++) hin[s] = 0.f;

    for (int c = 0; c < NCHK; c++) {
        size_t idx = ((size_t)c * BATCH + b) * DINNER + d;
        size_t o = idx * DSTATE;
        #pragma unroll
        for (int s = 0; s < DSTATE; s += 4)
            *(float4*)(g_hin + o + s) = make_float4(hin[s], hin[s+1], hin[s+2], hin[s+3]);
        if (c + 1 < NCHK) {
            float sd = g_sumd[idx];
            float hl[DSTATE];
            #pragma unroll
            for (int s = 0; s < DSTATE; s += 4)
                *(float4*)(hl + s) = *(const float4*)(g_hloc + o + s);
            if (fast) {
                float E = __expf(A0 * sd), p = E;
                #pragma unroll
                for (int s = 0; s < DSTATE; s++) { hin[s] = fmaf(p, hin[s], hl[s]); p *= E; }
            } else {
                #pragma unroll
                for (int s = 0; s < DSTATE; s++)
                    hin[s] = fmaf(__expf(Av[s] * sd), hin[s], hl[s]);
            }
        }
    }
}

__global__ void scan_pass2(const float* __restrict__ A_log,
                           const float* __restrict__ Dp)
{
    int gid = blockIdx.x * blockDim.x + threadIdx.x;
    if (gid >= BATCH * DINNER * NCHK) return;
    int d = gid & (DINNER - 1);
    int b = (gid >> 11) & (BATCH - 1);
    int c = gid >> 12;

    float Av[DSTATE], A0; bool fast;
    load_A(A_log, d, Av, A0, fast);
    float Dd = Dp[d];

    float h[DSTATE];
    size_t o = (size_t)gid * DSTATE;
    #pragma unroll
    for (int s = 0; s < DSTATE; s += 4)
        *(float4*)(h + s) = *(const float4*)(g_hin + o + s);

    size_t row = (size_t)b * LSEQ + (size_t)c * CLEN;
    #pragma unroll 2
    for (int l = 0; l < CLEN; l++, row++) {
        float dlt = g_delta[row * DINNER + d];
        float uu  = g_u[row * DINNER + d];
        float zz  = g_xz[row * (2 * DINNER) + DINNER + d];
        const float* xr = g_xdbl + row * XDBLW;
        float Bv[16], Cv[16];
        *(float4*)(Bv + 0)  = *(const float4*)(xr + 64);
        *(float4*)(Bv + 4)  = *(const float4*)(xr + 68);
        *(float4*)(Bv + 8)  = *(const float4*)(xr + 72);
        *(float4*)(Bv + 12) = *(const float4*)(xr + 76);
        *(float4*)(Cv + 0)  = *(const float4*)(xr + 80);
        *(float4*)(Cv + 4)  = *(const float4*)(xr + 84);
        *(float4*)(Cv + 8)  = *(const float4*)(xr + 88);
        *(float4*)(Cv + 12) = *(const float4*)(xr + 92);
        float du = dlt * uu;
        float y0 = 0.f, y1 = 0.f;
        if (fast) {
            float E = __expf(dlt * A0), p = E;
            #pragma unroll
            for (int s = 0; s < DSTATE; s++) {
                h[s] = fmaf(p, h[s], du * Bv[s]);
                if (s & 1) y1 = fmaf(h[s], Cv[s], y1); else y0 = fmaf(h[s], Cv[s], y0);
                p *= E;
            }
        } else {
            #pragma unroll
            for (int s = 0; s < DSTATE; s++) {
                float dA = __expf(dlt * Av[s]);
                h[s] = fmaf(dA, h[s], du * Bv[s]);
                if (s & 1) y1 = fmaf(h[s], Cv[s], y1); else y0 = fmaf(h[s], Cv[s], y0);
            }
        }
        float y = y0 + y1 + Dd * uu;
        float sig = 1.f / (1.f + __expf(-zz));
        float yv = y * (zz * sig);
        __nv_bfloat16 bh, bl;
        split1(yv, bh, bl);
        size_t oo = row * DINNER + d;
        g_ybh[oo] = bh;
        g_ybl[oo] = bl;
    }
}

// ================= launch =================
extern "C" void kernel_launch(void* const* d_in, const int* in_sizes, int n_in,
                              void* d_out, int out_size)
{
    const float* x      = (const float*)d_in[0];
    const float* norm_w = (const float*)d_in[1];
    const float* norm_b = (const float*)d_in[2];
    const float* W_in   = (const float*)d_in[3];
    const float* conv_w = (const float*)d_in[4];
    const float* conv_b = (const float*)d_in[5];
    const float* W_x    = (const float*)d_in[6];
    const float* W_dt   = (const float*)d_in[7];
    const float* b_dt   = (const float*)d_in[8];
    const float* A_log  = (const float*)d_in[9];
    const float* Dp     = (const float*)d_in[10];
    const float* W_out  = (const float*)d_in[11];
    float* out = (float*)d_out;

    cudaFuncSetAttribute(tc_gemm<128,3>, cudaFuncAttributeMaxDynamicSharedMemorySize, GEMM_SMEM);
    cudaFuncSetAttribute(tc_gemm<256,2>, cudaFuncAttributeMaxDynamicSharedMemorySize, GEMM_SMEM);

    // 0) fused weight conversions -> split planes
    cvt_all<<<(CVT_N3 + 255) / 256, 256>>>(W_in, W_x, W_dt, W_out);

    // 1) LayerNorm -> xn planes
    ln_kernel<<<ROWS, 256>>>(x, norm_w, norm_b);

    // 2) in_proj: g_xz = xn @ W_in^T   (N=4096, K=1024), 256-wide tiles
    tc_gemm<256,2><<<dim3(16, 32), 256, GEMM_SMEM>>>(PL_XN, PL_WIN, CF_XZ, nullptr,
        4096, 1024, DMODEL, DMODEL, 2 * DINNER, 1, 0, nullptr);

    // 3) conv + SiLU -> u (fp32 + planes), x4 vectorized
    conv_silu_kernel<<<(ROWS * DINNER / 4 + 255) / 256, 256>>>(conv_w, conv_b);

    // 4) x_proj: split-K x4 partials (N=96, K=2048), then reduce -> g_xdbl + planes
    tc_gemm<128,3><<<dim3(KSPL_X, 32), 256, GEMM_SMEM>>>(PL_U, PL_WX, CF_XPART, nullptr,
        96, 2048, DINNER, DINNER, XDBLW, KSPL_X, 4, nullptr);
    xproj_reduce<<<(ROWS * XDBLW / 4 + 255) / 256, 256>>>();

    // 5) dt_proj + softplus (N=2048, K=64), 256-wide tiles
    tc_gemm<256,2><<<dim3(8, 32), 256, GEMM_SMEM>>>(PL_XD, PL_WDT, CF_DELTA, nullptr,
        2048, 64, XDBLW, DTRANK, DINNER, 1, 2, b_dt);

    // 6) chunked scan: pass1 -> combine -> pass2
    scan_pass1<<<(BATCH * DINNER * NCHK + 255) / 256, 256>>>(A_log);
    scan_combine<<<(BATCH * DINNER + 255) / 256, 256>>>(A_log);
    scan_pass2<<<(BATCH * DINNER * NCHK + 255) / 256, 256>>>(A_log, Dp);

    // 7) out_proj + residual (N=1024, K=2048), 256-wide tiles -> single wave
    tc_gemm<256,2><<<dim3(4, 32), 256, GEMM_SMEM>>>(PL_YB, PL_WOUT, CF_EXT, out,
        1024, 2048, DINNER, DINNER, DMODEL, 1, 1, x);
}